// round 1
// baseline (speedup 1.0000x reference)
#include <cuda_runtime.h>

// Problem constants
#define BB   2
#define SS   1024
#define DIMM 1024
#define NH   16
#define HD   64
#define BS   (BB * SS)          // 2048 tokens
#define NEG_INF_F (-1000000000.0f)

// Scratch (static device globals; no allocation anywhere)
__device__ float g_q [BS * DIMM];
__device__ float g_k [BS * DIMM];
__device__ float g_v [BS * DIMM];
__device__ float g_ao[BS * DIMM];
__device__ float g_sc[33554432];   // B*NH*S*S = 2*16*1024*1024 floats (128 MB)

// ---------------------------------------------------------------------------
// Generic 128x128x8 SGEMM, 256 threads, 8x8 microtile. C = A(MxK) @ B(KxN).
// M,N multiples of 128; K multiple of 8. All row-major.
// ---------------------------------------------------------------------------
__global__ __launch_bounds__(256) void gemm128(const float* __restrict__ A,
                                               const float* __restrict__ Bw,
                                               float* __restrict__ C,
                                               int M, int N, int K)
{
    __shared__ float As[8][128];
    __shared__ float Bs[8][128];

    const int tid  = threadIdx.x;
    const int row0 = blockIdx.y * 128;
    const int col0 = blockIdx.x * 128;
    const int tx = tid & 15;
    const int ty = tid >> 4;

    const int aRow = tid >> 1;
    const int aCol = (tid & 1) * 4;
    const int bRow = tid >> 5;
    const int bCol = (tid & 31) * 4;

    float acc[8][8];
#pragma unroll
    for (int i = 0; i < 8; i++)
#pragma unroll
        for (int j = 0; j < 8; j++) acc[i][j] = 0.0f;

    const float* Aptr = A + (size_t)(row0 + aRow) * K + aCol;
    const float* Bptr = Bw + (size_t)bRow * N + col0 + bCol;

    for (int k0 = 0; k0 < K; k0 += 8) {
        float4 av = *(const float4*)(Aptr + k0);
        float4 bv = *(const float4*)(Bptr + (size_t)k0 * N);
        __syncthreads();
        As[aCol + 0][aRow] = av.x;
        As[aCol + 1][aRow] = av.y;
        As[aCol + 2][aRow] = av.z;
        As[aCol + 3][aRow] = av.w;
        *(float4*)&Bs[bRow][bCol] = bv;
        __syncthreads();
#pragma unroll
        for (int kk = 0; kk < 8; kk++) {
            float a[8], b[8];
            *(float4*)&a[0] = *(const float4*)&As[kk][ty * 8];
            *(float4*)&a[4] = *(const float4*)&As[kk][ty * 8 + 4];
            *(float4*)&b[0] = *(const float4*)&Bs[kk][tx * 8];
            *(float4*)&b[4] = *(const float4*)&Bs[kk][tx * 8 + 4];
#pragma unroll
            for (int i = 0; i < 8; i++)
#pragma unroll
                for (int j = 0; j < 8; j++)
                    acc[i][j] += a[i] * b[j];
        }
    }

#pragma unroll
    for (int i = 0; i < 8; i++) {
        float* cp = C + (size_t)(row0 + ty * 8 + i) * N + col0 + tx * 8;
        float4 v0 = make_float4(acc[i][0], acc[i][1], acc[i][2], acc[i][3]);
        float4 v1 = make_float4(acc[i][4], acc[i][5], acc[i][6], acc[i][7]);
        *(float4*)cp       = v0;
        *(float4*)(cp + 4) = v1;
    }
}

// ---------------------------------------------------------------------------
// RoPE instruction kernel.
// The 18 rotations close over 4-tuples {2m, 2m+1, 2m+32, 2m+33} per head.
// One thread per (head, m) handles both q and k in registers.
// Grid: BS blocks x 256 threads (16 heads x 16 m).
// ---------------------------------------------------------------------------
#define ROT(xx, yy, c, s) { float _t = (xx)*(c) - (yy)*(s); (yy) = (xx)*(s) + (yy)*(c); (xx) = _t; }

__global__ __launch_bounds__(256) void rope_kernel(float* __restrict__ q,
                                                   float* __restrict__ k,
                                                   const int* __restrict__ Hm,
                                                   const int* __restrict__ Bm,
                                                   const float* __restrict__ fc,
                                                   const float* __restrict__ fs)
{
    const int tok = blockIdx.x;          // b*S + s
    const int tid = threadIdx.x;
    const int h = tid >> 4;
    const int m = tid & 15;
    const int base = tok * DIMM + h * HD;

    float2 qab = *(const float2*)&q[base + 2 * m];
    float2 qcd = *(const float2*)&q[base + 2 * m + 32];
    float2 kab = *(const float2*)&k[base + 2 * m];
    float2 kcd = *(const float2*)&k[base + 2 * m + 32];

    // rot_H uses freqs row 1; pairs (2m,2m+1) -> cos[m], (2m+32,2m+33) -> cos[m+16]
    const float cH0 = fc[32 + m],      sH0 = fs[32 + m];
    const float cH1 = fc[32 + m + 16], sH1 = fs[32 + m + 16];
    // rot_B branch b uses freqs row b+1; pair (j, j+32) -> cos[j]
    const float cB0a = fc[32 + 2 * m],     sB0a = fs[32 + 2 * m];
    const float cB0b = fc[32 + 2 * m + 1], sB0b = fs[32 + 2 * m + 1];
    const float cB1a = fc[64 + 2 * m],     sB1a = fs[64 + 2 * m];
    const float cB1b = fc[64 + 2 * m + 1], sB1b = fs[64 + 2 * m + 1];

#pragma unroll
    for (int i = 0; i < 6; i++) {
        if (Hm[i * BS + tok]) {
            ROT(qab.x, qab.y, cH0, sH0); ROT(qcd.x, qcd.y, cH1, sH1);
            ROT(kab.x, kab.y, cH0, sH0); ROT(kcd.x, kcd.y, cH1, sH1);
        }
        if (Bm[(i * 2 + 0) * BS + tok]) {
            ROT(qab.x, qcd.x, cB0a, sB0a); ROT(qab.y, qcd.y, cB0b, sB0b);
            ROT(kab.x, kcd.x, cB0a, sB0a); ROT(kab.y, kcd.y, cB0b, sB0b);
        }
        if (Bm[(i * 2 + 1) * BS + tok]) {
            ROT(qab.x, qcd.x, cB1a, sB1a); ROT(qab.y, qcd.y, cB1b, sB1b);
            ROT(kab.x, kcd.x, cB1a, sB1a); ROT(kab.y, kcd.y, cB1b, sB1b);
        }
    }

    *(float2*)&q[base + 2 * m]      = qab;
    *(float2*)&q[base + 2 * m + 32] = qcd;
    *(float2*)&k[base + 2 * m]      = kab;
    *(float2*)&k[base + 2 * m + 32] = kcd;
}

// ---------------------------------------------------------------------------
// Scores: sc[bh, qi, kj] = mask ? 0.125*dot(q,k) : -1e9
// Block computes a 64x64 score tile for one (b,h). 256 threads, 4x4 microtile.
// ---------------------------------------------------------------------------
__global__ __launch_bounds__(256) void scores_kernel(const float* __restrict__ q,
                                                     const float* __restrict__ k,
                                                     const int* __restrict__ masks,
                                                     float* __restrict__ sc)
{
    __shared__ float Qs[64][68];   // [d][q-row]
    __shared__ float Ks[64][68];   // [d][k-row]

    const int bh = blockIdx.z;
    const int b = bh >> 4, h = bh & 15;
    const int q0 = blockIdx.y * 64;
    const int k0 = blockIdx.x * 64;
    const int tid = threadIdx.x;
    const int tx = tid & 15, ty = tid >> 4;

    {
        const int r0 = tid >> 4;           // 0..15
        const int c4 = (tid & 15) * 4;     // 0..60
#pragma unroll
        for (int i = 0; i < 4; i++) {
            int row = r0 + i * 16;
            float4 qv = *(const float4*)&q[(size_t)(b * SS + q0 + row) * DIMM + h * HD + c4];
            Qs[c4 + 0][row] = qv.x; Qs[c4 + 1][row] = qv.y;
            Qs[c4 + 2][row] = qv.z; Qs[c4 + 3][row] = qv.w;
            float4 kv = *(const float4*)&k[(size_t)(b * SS + k0 + row) * DIMM + h * HD + c4];
            Ks[c4 + 0][row] = kv.x; Ks[c4 + 1][row] = kv.y;
            Ks[c4 + 2][row] = kv.z; Ks[c4 + 3][row] = kv.w;
        }
    }
    __syncthreads();

    float acc[4][4];
#pragma unroll
    for (int i = 0; i < 4; i++)
#pragma unroll
        for (int j = 0; j < 4; j++) acc[i][j] = 0.0f;

#pragma unroll 16
    for (int d = 0; d < 64; d++) {
        float4 a  = *(const float4*)&Qs[d][ty * 4];
        float4 bb = *(const float4*)&Ks[d][tx * 4];
        float av[4] = {a.x, a.y, a.z, a.w};
        float bv[4] = {bb.x, bb.y, bb.z, bb.w};
#pragma unroll
        for (int i = 0; i < 4; i++)
#pragma unroll
            for (int j = 0; j < 4; j++)
                acc[i][j] += av[i] * bv[j];
    }

    const float scale = 0.125f;   // 1/sqrt(64)
#pragma unroll
    for (int i = 0; i < 4; i++) {
        int qi = q0 + ty * 4 + i;
        int4 mv = *(const int4*)&masks[(size_t)b * SS * SS + (size_t)qi * SS + k0 + tx * 4];
        float4 o;
        o.x = mv.x ? acc[i][0] * scale : NEG_INF_F;
        o.y = mv.y ? acc[i][1] * scale : NEG_INF_F;
        o.z = mv.z ? acc[i][2] * scale : NEG_INF_F;
        o.w = mv.w ? acc[i][3] * scale : NEG_INF_F;
        *(float4*)&sc[((size_t)bh * SS + qi) * SS + k0 + tx * 4] = o;
    }
}

// ---------------------------------------------------------------------------
// Row softmax over 1024 elements, in place. One block (256 threads) per row.
// ---------------------------------------------------------------------------
__global__ __launch_bounds__(256) void softmax_kernel(float* __restrict__ sc)
{
    const int row = blockIdx.x;
    float4* p = (float4*)(sc + (size_t)row * SS);
    const int tid = threadIdx.x;
    const int lane = tid & 31, w = tid >> 5;

    __shared__ float redm[8];
    __shared__ float reds[8];

    float4 v = p[tid];
    float mx = fmaxf(fmaxf(v.x, v.y), fmaxf(v.z, v.w));
#pragma unroll
    for (int o = 16; o > 0; o >>= 1) mx = fmaxf(mx, __shfl_xor_sync(0xffffffffu, mx, o));
    if (lane == 0) redm[w] = mx;
    __syncthreads();
    float M = redm[0];
#pragma unroll
    for (int i = 1; i < 8; i++) M = fmaxf(M, redm[i]);

    float e0 = __expf(v.x - M);
    float e1 = __expf(v.y - M);
    float e2 = __expf(v.z - M);
    float e3 = __expf(v.w - M);
    float s = e0 + e1 + e2 + e3;
#pragma unroll
    for (int o = 16; o > 0; o >>= 1) s += __shfl_xor_sync(0xffffffffu, s, o);
    if (lane == 0) reds[w] = s;
    __syncthreads();
    float total = 0.0f;
#pragma unroll
    for (int i = 0; i < 8; i++) total += reds[i];
    float inv = 1.0f / total;

    p[tid] = make_float4(e0 * inv, e1 * inv, e2 * inv, e3 * inv);
}

// ---------------------------------------------------------------------------
// PV: ao[b,q,h,d] = sum_k probs[bh,q,k] * v[b,k,h,d].
// Block = 64 queries x 64 dims (full head) for one (b,h). BK=16.
// ---------------------------------------------------------------------------
__global__ __launch_bounds__(256) void pv_kernel(const float* __restrict__ sc,
                                                 const float* __restrict__ v,
                                                 float* __restrict__ ao)
{
    __shared__ float Ps[16][68];   // [kk][q-row]
    __shared__ float Vs[16][64];   // [kk][d]

    const int bh = blockIdx.y;
    const int b = bh >> 4, h = bh & 15;
    const int q0 = blockIdx.x * 64;
    const int tid = threadIdx.x;
    const int tx = tid & 15, ty = tid >> 4;

    const int pr  = tid >> 2;         // 0..63
    const int pc4 = (tid & 3) * 4;    // 0..12
    const int vr  = tid >> 4;         // 0..15
    const int vc4 = (tid & 15) * 4;   // 0..60

    const float* prow = sc + ((size_t)bh * SS + q0 + pr) * SS + pc4;
    const float* vrow = v + (size_t)(b * SS + vr) * DIMM + h * HD + vc4;

    float acc[4][4];
#pragma unroll
    for (int i = 0; i < 4; i++)
#pragma unroll
        for (int j = 0; j < 4; j++) acc[i][j] = 0.0f;

    for (int k0 = 0; k0 < SS; k0 += 16) {
        float4 pv4 = *(const float4*)(prow + k0);
        float4 vv  = *(const float4*)(vrow + (size_t)k0 * DIMM);
        __syncthreads();
        Ps[pc4 + 0][pr] = pv4.x; Ps[pc4 + 1][pr] = pv4.y;
        Ps[pc4 + 2][pr] = pv4.z; Ps[pc4 + 3][pr] = pv4.w;
        *(float4*)&Vs[vr][vc4] = vv;
        __syncthreads();
#pragma unroll
        for (int kk = 0; kk < 16; kk++) {
            float4 a  = *(const float4*)&Ps[kk][ty * 4];
            float4 bb = *(const float4*)&Vs[kk][tx * 4];
            float av[4] = {a.x, a.y, a.z, a.w};
            float bv[4] = {bb.x, bb.y, bb.z, bb.w};
#pragma unroll
            for (int i = 0; i < 4; i++)
#pragma unroll
                for (int j = 0; j < 4; j++)
                    acc[i][j] += av[i] * bv[j];
        }
    }

#pragma unroll
    for (int i = 0; i < 4; i++) {
        float* op = ao + (size_t)(b * SS + q0 + ty * 4 + i) * DIMM + h * HD + tx * 4;
        *(float4*)op = make_float4(acc[i][0], acc[i][1], acc[i][2], acc[i][3]);
    }
}

// ---------------------------------------------------------------------------
extern "C" void kernel_launch(void* const* d_in, const int* in_sizes, int n_in,
                              void* d_out, int out_size)
{
    const float* x     = (const float*)d_in[0];
    const int*   masks = (const int*)d_in[1];
    const int*   Hm    = (const int*)d_in[2];
    const int*   Bm    = (const int*)d_in[3];
    const float* fc    = (const float*)d_in[4];
    const float* fs    = (const float*)d_in[5];
    const float* wq    = (const float*)d_in[6];
    const float* wk    = (const float*)d_in[7];
    const float* wv    = (const float*)d_in[8];
    const float* wo    = (const float*)d_in[9];
    float* out = (float*)d_out;

    float *gq, *gk, *gv, *gao, *gsc;
    cudaGetSymbolAddress((void**)&gq,  g_q);
    cudaGetSymbolAddress((void**)&gk,  g_k);
    cudaGetSymbolAddress((void**)&gv,  g_v);
    cudaGetSymbolAddress((void**)&gao, g_ao);
    cudaGetSymbolAddress((void**)&gsc, g_sc);

    dim3 gProj(DIMM / 128, BS / 128);          // (8, 16)

    gemm128<<<gProj, 256>>>(x, wq, gq, BS, DIMM, DIMM);
    gemm128<<<gProj, 256>>>(x, wk, gk, BS, DIMM, DIMM);
    gemm128<<<gProj, 256>>>(x, wv, gv, BS, DIMM, DIMM);

    rope_kernel<<<BS, 256>>>(gq, gk, Hm, Bm, fc, fs);

    scores_kernel<<<dim3(SS / 64, SS / 64, BB * NH), 256>>>(gq, gk, masks, gsc);
    softmax_kernel<<<BB * NH * SS, 256>>>(gsc);
    pv_kernel<<<dim3(SS / 64, BB * NH), 256>>>(gsc, gv, gao);

    gemm128<<<gProj, 256>>>(gao, wo, out, BS, DIMM, DIMM);
}

// round 3
// speedup vs baseline: 1.8237x; 1.8237x over previous
#include <cuda_runtime.h>
#include <cuda_bf16.h>

// Problem constants
#define BB   2
#define SS   1024
#define DIMM 1024
#define NH   16
#define HD   64
#define BS   (BB * SS)
#define NEG_INF_F (-1000000000.0f)

// ---------------------------------------------------------------------------
// Scratch (static device globals; no allocation anywhere)
// ---------------------------------------------------------------------------
__device__ float g_q [BS * DIMM];
__device__ float g_k [BS * DIMM];
__device__ float g_v [BS * DIMM];
__device__ float g_ao[BS * DIMM];
__device__ float g_sc[33554432];                 // 2*16*1024*1024 (128 MB)
__device__ __nv_bfloat16 g_xhi [BS * DIMM];
__device__ __nv_bfloat16 g_xlo [BS * DIMM];
__device__ __nv_bfloat16 g_aohi[BS * DIMM];
__device__ __nv_bfloat16 g_aolo[BS * DIMM];
__device__ __nv_bfloat16 g_whi [4 * DIMM * DIMM];  // transposed [n][k]
__device__ __nv_bfloat16 g_wlo [4 * DIMM * DIMM];

// ---------------------------------------------------------------------------
// PTX helpers (baseline ISA only: cp.async, ldmatrix, mma.sync — no `a` feats)
// ---------------------------------------------------------------------------
__device__ __forceinline__ unsigned smem_u32(const void* p) {
    unsigned a;
    asm("{ .reg .u64 t; cvta.to.shared.u64 t, %1; cvt.u32.u64 %0, t; }"
        : "=r"(a) : "l"(p));
    return a;
}

__device__ __forceinline__ void cp_async16(unsigned saddr, const void* gaddr) {
    asm volatile("cp.async.cg.shared.global [%0], [%1], 16;"
                 :: "r"(saddr), "l"(gaddr));
}
#define CP_COMMIT() asm volatile("cp.async.commit_group;")
template <int N>
__device__ __forceinline__ void cp_wait() {
    asm volatile("cp.async.wait_group %0;" :: "n"(N));
}

__device__ __forceinline__ void ldm_x4(unsigned addr, unsigned* r) {
    asm volatile("ldmatrix.sync.aligned.m8n8.x4.shared.b16 {%0,%1,%2,%3}, [%4];"
                 : "=r"(r[0]), "=r"(r[1]), "=r"(r[2]), "=r"(r[3]) : "r"(addr));
}

__device__ __forceinline__ void mma_bf16(float* c, const unsigned* a,
                                         const unsigned* b) {
    asm volatile(
        "mma.sync.aligned.m16n8k16.row.col.f32.bf16.bf16.f32 "
        "{%0,%1,%2,%3}, {%4,%5,%6,%7}, {%8,%9}, {%0,%1,%2,%3};"
        : "+f"(c[0]), "+f"(c[1]), "+f"(c[2]), "+f"(c[3])
        : "r"(a[0]), "r"(a[1]), "r"(a[2]), "r"(a[3]), "r"(b[0]), "r"(b[1]));
}

// ---------------------------------------------------------------------------
// Weight prep: fp32 w[k][n] -> bf16 hi/lo [n][k] (transposed, split)
// ---------------------------------------------------------------------------
__global__ __launch_bounds__(256) void prep_w(const float* __restrict__ w,
                                              __nv_bfloat16* __restrict__ hi,
                                              __nv_bfloat16* __restrict__ lo)
{
    __shared__ float t[32][33];
    const int tx = threadIdx.x & 31, ty = threadIdx.x >> 5;
    const int n0 = blockIdx.x * 32, k0 = blockIdx.y * 32;
#pragma unroll
    for (int i = 0; i < 4; i++)
        t[ty + 8 * i][tx] = w[(size_t)(k0 + ty + 8 * i) * DIMM + n0 + tx];
    __syncthreads();
#pragma unroll
    for (int i = 0; i < 4; i++) {
        float v = t[tx][ty + 8 * i];
        __nv_bfloat16 h = __float2bfloat16_rn(v);
        float r = v - __bfloat162float(h);
        size_t o = (size_t)(n0 + ty + 8 * i) * DIMM + k0 + tx;
        hi[o] = h;
        lo[o] = __float2bfloat16_rn(r);
    }
}

// ---------------------------------------------------------------------------
// Activation split: fp32 -> bf16 hi/lo
// ---------------------------------------------------------------------------
__global__ __launch_bounds__(256) void split_f32(const float4* __restrict__ in,
                                                 __nv_bfloat16* __restrict__ hi,
                                                 __nv_bfloat16* __restrict__ lo)
{
    const int i = blockIdx.x * 256 + threadIdx.x;
    float4 v = in[i];
    __nv_bfloat16 h0 = __float2bfloat16_rn(v.x), h1 = __float2bfloat16_rn(v.y);
    __nv_bfloat16 h2 = __float2bfloat16_rn(v.z), h3 = __float2bfloat16_rn(v.w);
    __nv_bfloat16 l0 = __float2bfloat16_rn(v.x - __bfloat162float(h0));
    __nv_bfloat16 l1 = __float2bfloat16_rn(v.y - __bfloat162float(h1));
    __nv_bfloat16 l2 = __float2bfloat16_rn(v.z - __bfloat162float(h2));
    __nv_bfloat16 l3 = __float2bfloat16_rn(v.w - __bfloat162float(h3));
    unsigned hw0 = (unsigned)__bfloat16_as_ushort(h0) | ((unsigned)__bfloat16_as_ushort(h1) << 16);
    unsigned hw1 = (unsigned)__bfloat16_as_ushort(h2) | ((unsigned)__bfloat16_as_ushort(h3) << 16);
    unsigned lw0 = (unsigned)__bfloat16_as_ushort(l0) | ((unsigned)__bfloat16_as_ushort(l1) << 16);
    unsigned lw1 = (unsigned)__bfloat16_as_ushort(l2) | ((unsigned)__bfloat16_as_ushort(l3) << 16);
    ((uint2*)hi)[i] = make_uint2(hw0, hw1);
    ((uint2*)lo)[i] = make_uint2(lw0, lw1);
}

// ---------------------------------------------------------------------------
// MMA GEMM: C[M,N] fp32 = (Ahi+Alo)[M,K] @ (Bhi+Blo)[N,K]^T
// 128x128 CTA tile, BK=32, 3-stage cp.async pipeline, bf16x2 split (3 passes).
// 8 warps: wm = wid&1 (2 in M, 64 rows each), wn = wid>>1 (4 in N, 32 cols).
// ---------------------------------------------------------------------------
#define BK        32
#define ROW_ELEMS 40                   // 32 + 8 pad (80 B rows, conflict-free)
#define ROW_BYTES (ROW_ELEMS * 2)
#define TILE_B    (128 * ROW_BYTES)    // 10240 B
#define STAGE_B   (4 * TILE_B)         // Ahi, Alo, Bhi, Blo
#define NSTAGE    3
#define GEMM_SMEM (NSTAGE * STAGE_B)   // 122880 B

__global__ __launch_bounds__(256) void gemm_mma(
    const __nv_bfloat16* __restrict__ Ahi, const __nv_bfloat16* __restrict__ Alo,
    const __nv_bfloat16* __restrict__ Bhi, const __nv_bfloat16* __restrict__ Blo,
    float* __restrict__ C, int M, int N, int K)
{
    extern __shared__ char smem[];
    const unsigned sb = smem_u32(smem);

    const int tid  = threadIdx.x;
    const int lane = tid & 31;
    const int wid  = tid >> 5;
    const int wm   = wid & 1;        // 0..1  (64 rows)
    const int wn   = wid >> 1;       // 0..3  (32 cols)
    const int row0 = blockIdx.y * 128;
    const int col0 = blockIdx.x * 128;

    // ---- loader mapping: 512 16B-segments per tile, 2 per thread ----
    // task t: row = t>>2 (0..127), seg = t&3 (16B each = 8 bf16)
    const int t0r = tid >> 2, t0s = tid & 3;               // task tid
    const int t1r = t0r + 64;                              // task tid+256
    const size_t gA0 = (size_t)(row0 + t0r) * K + t0s * 8;
    const size_t gA1 = (size_t)(row0 + t1r) * K + t0s * 8;
    const size_t gB0 = (size_t)(col0 + t0r) * K + t0s * 8;
    const size_t gB1 = (size_t)(col0 + t1r) * K + t0s * 8;
    const unsigned s0 = t0r * ROW_BYTES + t0s * 16;
    const unsigned s1 = t1r * ROW_BYTES + t0s * 16;

#define LOAD_CHUNK(c, stg) do {                                              \
    const int kk = (c) * BK;                                                 \
    unsigned base = sb + (stg) * STAGE_B;                                    \
    cp_async16(base + 0 * TILE_B + s0, Ahi + gA0 + kk);                      \
    cp_async16(base + 0 * TILE_B + s1, Ahi + gA1 + kk);                      \
    cp_async16(base + 1 * TILE_B + s0, Alo + gA0 + kk);                      \
    cp_async16(base + 1 * TILE_B + s1, Alo + gA1 + kk);                      \
    cp_async16(base + 2 * TILE_B + s0, Bhi + gB0 + kk);                      \
    cp_async16(base + 2 * TILE_B + s1, Bhi + gB1 + kk);                      \
    cp_async16(base + 3 * TILE_B + s0, Blo + gB0 + kk);                      \
    cp_async16(base + 3 * TILE_B + s1, Blo + gB1 + kk);                      \
} while (0)

    float acc[4][4][4];
#pragma unroll
    for (int i = 0; i < 4; i++)
#pragma unroll
        for (int j = 0; j < 4; j++)
#pragma unroll
            for (int q = 0; q < 4; q++) acc[i][j][q] = 0.0f;

    // ldmatrix lane addressing (within a tile, kstep handled by +32B)
    const int l7 = lane & 7, m4 = lane >> 3;
    // A x4: rows m0 + (m4&1)*8 + l7, kB = (m4>>1)*16
    const unsigned aoff = (wm * 64 + (m4 & 1) * 8 + l7) * ROW_BYTES + (m4 >> 1) * 16;
    // B x4: rows n0 + (m4&2?8:0) + l7, kB = (m4&1)*16
    const unsigned boff = (wn * 32 + ((m4 & 2) ? 8 : 0) + l7) * ROW_BYTES + (m4 & 1) * 16;

    const int NCH = K / BK;   // 32

    LOAD_CHUNK(0, 0); CP_COMMIT();
    LOAD_CHUNK(1, 1); CP_COMMIT();

    for (int c = 0; c < NCH; c++) {
        cp_wait<1>();
        __syncthreads();

        if (c + 2 < NCH) LOAD_CHUNK(c + 2, (c + 2) % NSTAGE);
        CP_COMMIT();

        const unsigned stg = sb + (c % NSTAGE) * STAGE_B;
#pragma unroll
        for (int ks = 0; ks < 2; ks++) {
            const unsigned kb = ks * 32;   // 16 bf16 = 32 B per kstep
            unsigned ah[4][4], al[4][4], bh[2][4], bl[2][4];
#pragma unroll
            for (int mi = 0; mi < 4; mi++) {
                unsigned ad = stg + aoff + mi * (16 * ROW_BYTES) + kb;
                ldm_x4(ad + 0 * TILE_B, ah[mi]);
                ldm_x4(ad + 1 * TILE_B, al[mi]);
            }
#pragma unroll
            for (int ng = 0; ng < 2; ng++) {
                unsigned bd = stg + boff + ng * (16 * ROW_BYTES) + kb;
                ldm_x4(bd + 2 * TILE_B, bh[ng]);
                ldm_x4(bd + 3 * TILE_B, bl[ng]);
            }
#pragma unroll
            for (int mi = 0; mi < 4; mi++)
#pragma unroll
                for (int ni = 0; ni < 4; ni++) {
                    const int ng = ni >> 1, half = (ni & 1) * 2;
                    unsigned bhr[2] = { bh[ng][half], bh[ng][half + 1] };
                    unsigned blr[2] = { bl[ng][half], bl[ng][half + 1] };
                    mma_bf16(acc[mi][ni], ah[mi], bhr);
                    mma_bf16(acc[mi][ni], ah[mi], blr);
                    mma_bf16(acc[mi][ni], al[mi], bhr);
                }
        }
        __syncthreads();
    }

    // Epilogue: C fragment c0,c1 at (row, col), c2,c3 at (row+8, col)
    const int erow = row0 + wm * 64 + (lane >> 2);
    const int ecol = col0 + wn * 32 + (lane & 3) * 2;
#pragma unroll
    for (int mi = 0; mi < 4; mi++)
#pragma unroll
        for (int ni = 0; ni < 4; ni++) {
            float* p0 = C + (size_t)(erow + mi * 16) * N + ecol + ni * 8;
            float* p1 = p0 + 8 * N;
            p0[0] = acc[mi][ni][0]; p0[1] = acc[mi][ni][1];
            p1[0] = acc[mi][ni][2]; p1[1] = acc[mi][ni][3];
        }
#undef LOAD_CHUNK
}

// ---------------------------------------------------------------------------
// RoPE instruction kernel (unchanged, passed R1)
// ---------------------------------------------------------------------------
#define ROT(xx, yy, c, s) { float _t = (xx)*(c) - (yy)*(s); (yy) = (xx)*(s) + (yy)*(c); (xx) = _t; }

__global__ __launch_bounds__(256) void rope_kernel(float* __restrict__ q,
                                                   float* __restrict__ k,
                                                   const int* __restrict__ Hm,
                                                   const int* __restrict__ Bm,
                                                   const float* __restrict__ fc,
                                                   const float* __restrict__ fs)
{
    const int tok = blockIdx.x;
    const int tid = threadIdx.x;
    const int h = tid >> 4;
    const int m = tid & 15;
    const int base = tok * DIMM + h * HD;

    float2 qab = *(const float2*)&q[base + 2 * m];
    float2 qcd = *(const float2*)&q[base + 2 * m + 32];
    float2 kab = *(const float2*)&k[base + 2 * m];
    float2 kcd = *(const float2*)&k[base + 2 * m + 32];

    const float cH0 = fc[32 + m],      sH0 = fs[32 + m];
    const float cH1 = fc[32 + m + 16], sH1 = fs[32 + m + 16];
    const float cB0a = fc[32 + 2 * m],     sB0a = fs[32 + 2 * m];
    const float cB0b = fc[32 + 2 * m + 1], sB0b = fs[32 + 2 * m + 1];
    const float cB1a = fc[64 + 2 * m],     sB1a = fs[64 + 2 * m];
    const float cB1b = fc[64 + 2 * m + 1], sB1b = fs[64 + 2 * m + 1];

#pragma unroll
    for (int i = 0; i < 6; i++) {
        if (Hm[i * BS + tok]) {
            ROT(qab.x, qab.y, cH0, sH0); ROT(qcd.x, qcd.y, cH1, sH1);
            ROT(kab.x, kab.y, cH0, sH0); ROT(kcd.x, kcd.y, cH1, sH1);
        }
        if (Bm[(i * 2 + 0) * BS + tok]) {
            ROT(qab.x, qcd.x, cB0a, sB0a); ROT(qab.y, qcd.y, cB0b, sB0b);
            ROT(kab.x, kcd.x, cB0a, sB0a); ROT(kab.y, kcd.y, cB0b, sB0b);
        }
        if (Bm[(i * 2 + 1) * BS + tok]) {
            ROT(qab.x, qcd.x, cB1a, sB1a); ROT(qab.y, qcd.y, cB1b, sB1b);
            ROT(kab.x, kcd.x, cB1a, sB1a); ROT(kab.y, kcd.y, cB1b, sB1b);
        }
    }

    *(float2*)&q[base + 2 * m]      = qab;
    *(float2*)&q[base + 2 * m + 32] = qcd;
    *(float2*)&k[base + 2 * m]      = kab;
    *(float2*)&k[base + 2 * m + 32] = kcd;
}

// ---------------------------------------------------------------------------
// Scores / softmax / PV (unchanged, passed R1)
// ---------------------------------------------------------------------------
__global__ __launch_bounds__(256) void scores_kernel(const float* __restrict__ q,
                                                     const float* __restrict__ k,
                                                     const int* __restrict__ masks,
                                                     float* __restrict__ sc)
{
    __shared__ float Qs[64][68];
    __shared__ float Ks[64][68];

    const int bh = blockIdx.z;
    const int b = bh >> 4, h = bh & 15;
    const int q0 = blockIdx.y * 64;
    const int k0 = blockIdx.x * 64;
    const int tid = threadIdx.x;
    const int tx = tid & 15, ty = tid >> 4;

    {
        const int r0 = tid >> 4;
        const int c4 = (tid & 15) * 4;
#pragma unroll
        for (int i = 0; i < 4; i++) {
            int row = r0 + i * 16;
            float4 qv = *(const float4*)&q[(size_t)(b * SS + q0 + row) * DIMM + h * HD + c4];
            Qs[c4 + 0][row] = qv.x; Qs[c4 + 1][row] = qv.y;
            Qs[c4 + 2][row] = qv.z; Qs[c4 + 3][row] = qv.w;
            float4 kv = *(const float4*)&k[(size_t)(b * SS + k0 + row) * DIMM + h * HD + c4];
            Ks[c4 + 0][row] = kv.x; Ks[c4 + 1][row] = kv.y;
            Ks[c4 + 2][row] = kv.z; Ks[c4 + 3][row] = kv.w;
        }
    }
    __syncthreads();

    float acc[4][4];
#pragma unroll
    for (int i = 0; i < 4; i++)
#pragma unroll
        for (int j = 0; j < 4; j++) acc[i][j] = 0.0f;

#pragma unroll 16
    for (int d = 0; d < 64; d++) {
        float4 a  = *(const float4*)&Qs[d][ty * 4];
        float4 bb = *(const float4*)&Ks[d][tx * 4];
        float av[4] = {a.x, a.y, a.z, a.w};
        float bv[4] = {bb.x, bb.y, bb.z, bb.w};
#pragma unroll
        for (int i = 0; i < 4; i++)
#pragma unroll
            for (int j = 0; j < 4; j++)
                acc[i][j] += av[i] * bv[j];
    }

    const float scale = 0.125f;
#pragma unroll
    for (int i = 0; i < 4; i++) {
        int qi = q0 + ty * 4 + i;
        int4 mv = *(const int4*)&masks[(size_t)b * SS * SS + (size_t)qi * SS + k0 + tx * 4];
        float4 o;
        o.x = mv.x ? acc[i][0] * scale : NEG_INF_F;
        o.y = mv.y ? acc[i][1] * scale : NEG_INF_F;
        o.z = mv.z ? acc[i][2] * scale : NEG_INF_F;
        o.w = mv.w ? acc[i][3] * scale : NEG_INF_F;
        *(float4*)&sc[((size_t)bh * SS + qi) * SS + k0 + tx * 4] = o;
    }
}

__global__ __launch_bounds__(256) void softmax_kernel(float* __restrict__ sc)
{
    const int row = blockIdx.x;
    float4* p = (float4*)(sc + (size_t)row * SS);
    const int tid = threadIdx.x;
    const int lane = tid & 31, w = tid >> 5;

    __shared__ float redm[8];
    __shared__ float reds[8];

    float4 v = p[tid];
    float mx = fmaxf(fmaxf(v.x, v.y), fmaxf(v.z, v.w));
#pragma unroll
    for (int o = 16; o > 0; o >>= 1) mx = fmaxf(mx, __shfl_xor_sync(0xffffffffu, mx, o));
    if (lane == 0) redm[w] = mx;
    __syncthreads();
    float M = redm[0];
#pragma unroll
    for (int i = 1; i < 8; i++) M = fmaxf(M, redm[i]);

    float e0 = __expf(v.x - M);
    float e1 = __expf(v.y - M);
    float e2 = __expf(v.z - M);
    float e3 = __expf(v.w - M);
    float s = e0 + e1 + e2 + e3;
#pragma unroll
    for (int o = 16; o > 0; o >>= 1) s += __shfl_xor_sync(0xffffffffu, s, o);
    if (lane == 0) reds[w] = s;
    __syncthreads();
    float total = 0.0f;
#pragma unroll
    for (int i = 0; i < 8; i++) total += reds[i];
    float inv = 1.0f / total;

    p[tid] = make_float4(e0 * inv, e1 * inv, e2 * inv, e3 * inv);
}

__global__ __launch_bounds__(256) void pv_kernel(const float* __restrict__ sc,
                                                 const float* __restrict__ v,
                                                 float* __restrict__ ao)
{
    __shared__ float Ps[16][68];
    __shared__ float Vs[16][64];

    const int bh = blockIdx.y;
    const int b = bh >> 4, h = bh & 15;
    const int q0 = blockIdx.x * 64;
    const int tid = threadIdx.x;
    const int tx = tid & 15, ty = tid >> 4;

    const int pr  = tid >> 2;
    const int pc4 = (tid & 3) * 4;
    const int vr  = tid >> 4;
    const int vc4 = (tid & 15) * 4;

    const float* prow = sc + ((size_t)bh * SS + q0 + pr) * SS + pc4;
    const float* vrow = v + (size_t)(b * SS + vr) * DIMM + h * HD + vc4;

    float acc[4][4];
#pragma unroll
    for (int i = 0; i < 4; i++)
#pragma unroll
        for (int j = 0; j < 4; j++) acc[i][j] = 0.0f;

    for (int k0 = 0; k0 < SS; k0 += 16) {
        float4 pv4 = *(const float4*)(prow + k0);
        float4 vv  = *(const float4*)(vrow + (size_t)k0 * DIMM);
        __syncthreads();
        Ps[pc4 + 0][pr] = pv4.x; Ps[pc4 + 1][pr] = pv4.y;
        Ps[pc4 + 2][pr] = pv4.z; Ps[pc4 + 3][pr] = pv4.w;
        *(float4*)&Vs[vr][vc4] = vv;
        __syncthreads();
#pragma unroll
        for (int kk = 0; kk < 16; kk++) {
            float4 a  = *(const float4*)&Ps[kk][ty * 4];
            float4 bb = *(const float4*)&Vs[kk][tx * 4];
            float av[4] = {a.x, a.y, a.z, a.w};
            float bv[4] = {bb.x, bb.y, bb.z, bb.w};
#pragma unroll
            for (int i = 0; i < 4; i++)
#pragma unroll
                for (int j = 0; j < 4; j++)
                    acc[i][j] += av[i] * bv[j];
        }
    }

#pragma unroll
    for (int i = 0; i < 4; i++) {
        float* op = ao + (size_t)(b * SS + q0 + ty * 4 + i) * DIMM + h * HD + tx * 4;
        *(float4*)op = make_float4(acc[i][0], acc[i][1], acc[i][2], acc[i][3]);
    }
}

// ---------------------------------------------------------------------------
extern "C" void kernel_launch(void* const* d_in, const int* in_sizes, int n_in,
                              void* d_out, int out_size)
{
    const float* x     = (const float*)d_in[0];
    const int*   masks = (const int*)d_in[1];
    const int*   Hm    = (const int*)d_in[2];
    const int*   Bm    = (const int*)d_in[3];
    const float* fc    = (const float*)d_in[4];
    const float* fs    = (const float*)d_in[5];
    const float* wq    = (const float*)d_in[6];
    const float* wk    = (const float*)d_in[7];
    const float* wv    = (const float*)d_in[8];
    const float* wo    = (const float*)d_in[9];
    float* out = (float*)d_out;

    float *gq, *gk, *gv, *gao, *gsc;
    __nv_bfloat16 *xhi, *xlo, *aohi, *aolo, *whi, *wlo;
    cudaGetSymbolAddress((void**)&gq,   g_q);
    cudaGetSymbolAddress((void**)&gk,   g_k);
    cudaGetSymbolAddress((void**)&gv,   g_v);
    cudaGetSymbolAddress((void**)&gao,  g_ao);
    cudaGetSymbolAddress((void**)&gsc,  g_sc);
    cudaGetSymbolAddress((void**)&xhi,  g_xhi);
    cudaGetSymbolAddress((void**)&xlo,  g_xlo);
    cudaGetSymbolAddress((void**)&aohi, g_aohi);
    cudaGetSymbolAddress((void**)&aolo, g_aolo);
    cudaGetSymbolAddress((void**)&whi,  g_whi);
    cudaGetSymbolAddress((void**)&wlo,  g_wlo);

    static bool attr_done = false;
    if (!attr_done) {
        cudaFuncSetAttribute(gemm_mma, cudaFuncAttributeMaxDynamicSharedMemorySize,
                             GEMM_SMEM);
        attr_done = true;
    }

    const size_t WSZ = (size_t)DIMM * DIMM;
    dim3 gPrep(32, 32);
    prep_w<<<gPrep, 256>>>(wq, whi + 0 * WSZ, wlo + 0 * WSZ);
    prep_w<<<gPrep, 256>>>(wk, whi + 1 * WSZ, wlo + 1 * WSZ);
    prep_w<<<gPrep, 256>>>(wv, whi + 2 * WSZ, wlo + 2 * WSZ);
    prep_w<<<gPrep, 256>>>(wo, whi + 3 * WSZ, wlo + 3 * WSZ);

    split_f32<<<BS * DIMM / 4 / 256, 256>>>((const float4*)x, xhi, xlo);

    dim3 gGemm(DIMM / 128, BS / 128);   // (8, 16)
    gemm_mma<<<gGemm, 256, GEMM_SMEM>>>(xhi, xlo, whi + 0 * WSZ, wlo + 0 * WSZ, gq, BS, DIMM, DIMM);
    gemm_mma<<<gGemm, 256, GEMM_SMEM>>>(xhi, xlo, whi + 1 * WSZ, wlo + 1 * WSZ, gk, BS, DIMM, DIMM);
    gemm_mma<<<gGemm, 256, GEMM_SMEM>>>(xhi, xlo, whi + 2 * WSZ, wlo + 2 * WSZ, gv, BS, DIMM, DIMM);

    rope_kernel<<<BS, 256>>>(gq, gk, Hm, Bm, fc, fs);

    scores_kernel<<<dim3(SS / 64, SS / 64, BB * NH), 256>>>(gq, gk, masks, gsc);
    softmax_kernel<<<BB * NH * SS, 256>>>(gsc);
    pv_kernel<<<dim3(SS / 64, BB * NH), 256>>>(gsc, gv, gao);

    split_f32<<<BS * DIMM / 4 / 256, 256>>>((const float4*)gao, aohi, aolo);
    gemm_mma<<<gGemm, 256, GEMM_SMEM>>>(aohi, aolo, whi + 3 * WSZ, wlo + 3 * WSZ, out, BS, DIMM, DIMM);
}

// round 5
// speedup vs baseline: 2.6252x; 1.4395x over previous
#include <cuda_runtime.h>
#include <cuda_bf16.h>

// Problem constants
#define BB   2
#define SS   1024
#define DIMM 1024
#define NH   16
#define HD   64
#define BS   (BB * SS)
#define NEG_INF_F (-1000000000.0f)

// ---------------------------------------------------------------------------
// Scratch (static device globals; no allocation anywhere)
// ---------------------------------------------------------------------------
__device__ float g_q [BS * DIMM];
__device__ float g_k [BS * DIMM];
__device__ float g_v [BS * DIMM];
__device__ float g_ao[BS * DIMM];
__device__ float g_sc[33554432];                 // 2*16*1024*1024 (128 MB)
__device__ __nv_bfloat16 g_xhi [BS * DIMM];
__device__ __nv_bfloat16 g_xlo [BS * DIMM];
__device__ __nv_bfloat16 g_aohi[BS * DIMM];
__device__ __nv_bfloat16 g_aolo[BS * DIMM];
__device__ __nv_bfloat16 g_whi [4 * DIMM * DIMM];  // transposed [n][k]
__device__ __nv_bfloat16 g_wlo [4 * DIMM * DIMM];
__device__ __nv_bfloat16 g_qhi [BS * DIMM];
__device__ __nv_bfloat16 g_qlo [BS * DIMM];
__device__ __nv_bfloat16 g_khi [BS * DIMM];
__device__ __nv_bfloat16 g_klo [BS * DIMM];
__device__ __nv_bfloat16 g_vThi[BB * NH * HD * SS];   // [bh][d][k]
__device__ __nv_bfloat16 g_vTlo[BB * NH * HD * SS];
__device__ __nv_bfloat16 g_phi [33554432];            // probs hi (64 MB)
__device__ __nv_bfloat16 g_plo [33554432];            // probs lo

// ---------------------------------------------------------------------------
// PTX helpers (baseline ISA only)
// ---------------------------------------------------------------------------
__device__ __forceinline__ unsigned smem_u32(const void* p) {
    unsigned a;
    asm("{ .reg .u64 t; cvta.to.shared.u64 t, %1; cvt.u32.u64 %0, t; }"
        : "=r"(a) : "l"(p));
    return a;
}

__device__ __forceinline__ void cp_async16(unsigned saddr, const void* gaddr) {
    asm volatile("cp.async.cg.shared.global [%0], [%1], 16;"
                 :: "r"(saddr), "l"(gaddr));
}
#define CP_COMMIT() asm volatile("cp.async.commit_group;")
template <int N>
__device__ __forceinline__ void cp_wait() {
    asm volatile("cp.async.wait_group %0;" :: "n"(N));
}

__device__ __forceinline__ void ldm_x4(unsigned addr, unsigned* r) {
    asm volatile("ldmatrix.sync.aligned.m8n8.x4.shared.b16 {%0,%1,%2,%3}, [%4];"
                 : "=r"(r[0]), "=r"(r[1]), "=r"(r[2]), "=r"(r[3]) : "r"(addr));
}

__device__ __forceinline__ void mma_bf16(float* c, const unsigned* a,
                                         const unsigned* b) {
    asm volatile(
        "mma.sync.aligned.m16n8k16.row.col.f32.bf16.bf16.f32 "
        "{%0,%1,%2,%3}, {%4,%5,%6,%7}, {%8,%9}, {%0,%1,%2,%3};"
        : "+f"(c[0]), "+f"(c[1]), "+f"(c[2]), "+f"(c[3])
        : "r"(a[0]), "r"(a[1]), "r"(a[2]), "r"(a[3]), "r"(b[0]), "r"(b[1]));
}

// ---------------------------------------------------------------------------
// Weight prep: fp32 w[k][n] -> bf16 hi/lo [n][k] (transposed, split)
// ---------------------------------------------------------------------------
__global__ __launch_bounds__(256) void prep_w(const float* __restrict__ w,
                                              __nv_bfloat16* __restrict__ hi,
                                              __nv_bfloat16* __restrict__ lo)
{
    __shared__ float t[32][33];
    const int tx = threadIdx.x & 31, ty = threadIdx.x >> 5;
    const int n0 = blockIdx.x * 32, k0 = blockIdx.y * 32;
#pragma unroll
    for (int i = 0; i < 4; i++)
        t[ty + 8 * i][tx] = w[(size_t)(k0 + ty + 8 * i) * DIMM + n0 + tx];
    __syncthreads();
#pragma unroll
    for (int i = 0; i < 4; i++) {
        float v = t[tx][ty + 8 * i];
        __nv_bfloat16 h = __float2bfloat16_rn(v);
        float r = v - __bfloat162float(h);
        size_t o = (size_t)(n0 + ty + 8 * i) * DIMM + k0 + tx;
        hi[o] = h;
        lo[o] = __float2bfloat16_rn(r);
    }
}

// ---------------------------------------------------------------------------
// Activation split: fp32 -> bf16 hi/lo
// ---------------------------------------------------------------------------
__global__ __launch_bounds__(256) void split_f32(const float4* __restrict__ in,
                                                 __nv_bfloat16* __restrict__ hi,
                                                 __nv_bfloat16* __restrict__ lo)
{
    const int i = blockIdx.x * 256 + threadIdx.x;
    float4 v = in[i];
    __nv_bfloat16 h0 = __float2bfloat16_rn(v.x), h1 = __float2bfloat16_rn(v.y);
    __nv_bfloat16 h2 = __float2bfloat16_rn(v.z), h3 = __float2bfloat16_rn(v.w);
    __nv_bfloat16 l0 = __float2bfloat16_rn(v.x - __bfloat162float(h0));
    __nv_bfloat16 l1 = __float2bfloat16_rn(v.y - __bfloat162float(h1));
    __nv_bfloat16 l2 = __float2bfloat16_rn(v.z - __bfloat162float(h2));
    __nv_bfloat16 l3 = __float2bfloat16_rn(v.w - __bfloat162float(h3));
    unsigned hw0 = (unsigned)__bfloat16_as_ushort(h0) | ((unsigned)__bfloat16_as_ushort(h1) << 16);
    unsigned hw1 = (unsigned)__bfloat16_as_ushort(h2) | ((unsigned)__bfloat16_as_ushort(h3) << 16);
    unsigned lw0 = (unsigned)__bfloat16_as_ushort(l0) | ((unsigned)__bfloat16_as_ushort(l1) << 16);
    unsigned lw1 = (unsigned)__bfloat16_as_ushort(l2) | ((unsigned)__bfloat16_as_ushort(l3) << 16);
    ((uint2*)hi)[i] = make_uint2(hw0, hw1);
    ((uint2*)lo)[i] = make_uint2(lw0, lw1);
}

// ---------------------------------------------------------------------------
// V transpose+split: v[b*SS+k][h*HD+d] -> vT[bh][d][k] (bf16 hi/lo)
// ---------------------------------------------------------------------------
__global__ __launch_bounds__(256) void vt_split(const float* __restrict__ v,
                                                __nv_bfloat16* __restrict__ hi,
                                                __nv_bfloat16* __restrict__ lo)
{
    __shared__ float t[32][33];
    const int tx = threadIdx.x & 31, ty = threadIdx.x >> 5;
    const int bh = blockIdx.z, b = bh >> 4, h = bh & 15;
    const int k0 = blockIdx.x * 32, d0 = blockIdx.y * 32;
#pragma unroll
    for (int i = 0; i < 4; i++)
        t[ty + 8 * i][tx] = v[(size_t)(b * SS + k0 + ty + 8 * i) * DIMM + h * HD + d0 + tx];
    __syncthreads();
#pragma unroll
    for (int i = 0; i < 4; i++) {
        float val = t[tx][ty + 8 * i];
        __nv_bfloat16 hh = __float2bfloat16_rn(val);
        float r = val - __bfloat162float(hh);
        size_t o = (size_t)bh * HD * SS + (size_t)(d0 + ty + 8 * i) * SS + k0 + tx;
        hi[o] = hh;
        lo[o] = __float2bfloat16_rn(r);
    }
}

// ---------------------------------------------------------------------------
// MMA GEMM: C[M,N] fp32 = (Ahi+Alo)[M,K] @ (Bhi+Blo)[N,K]^T  (projections)
// ---------------------------------------------------------------------------
#define BK        32
#define ROW_ELEMS 40
#define ROW_BYTES (ROW_ELEMS * 2)
#define TILE_B    (128 * ROW_BYTES)
#define STAGE_B   (4 * TILE_B)
#define NSTAGE    3
#define GEMM_SMEM (NSTAGE * STAGE_B)

__global__ __launch_bounds__(256) void gemm_mma(
    const __nv_bfloat16* __restrict__ Ahi, const __nv_bfloat16* __restrict__ Alo,
    const __nv_bfloat16* __restrict__ Bhi, const __nv_bfloat16* __restrict__ Blo,
    float* __restrict__ C, int M, int N, int K)
{
    extern __shared__ char smem[];
    const unsigned sb = smem_u32(smem);

    const int tid  = threadIdx.x;
    const int lane = tid & 31;
    const int wid  = tid >> 5;
    const int wm   = wid & 1;
    const int wn   = wid >> 1;
    const int row0 = blockIdx.y * 128;
    const int col0 = blockIdx.x * 128;

    const int t0r = tid >> 2, t0s = tid & 3;
    const int t1r = t0r + 64;
    const size_t gA0 = (size_t)(row0 + t0r) * K + t0s * 8;
    const size_t gA1 = (size_t)(row0 + t1r) * K + t0s * 8;
    const size_t gB0 = (size_t)(col0 + t0r) * K + t0s * 8;
    const size_t gB1 = (size_t)(col0 + t1r) * K + t0s * 8;
    const unsigned s0 = t0r * ROW_BYTES + t0s * 16;
    const unsigned s1 = t1r * ROW_BYTES + t0s * 16;

#define LOAD_CHUNK(c, stg) do {                                              \
    const int kk = (c) * BK;                                                 \
    unsigned base = sb + (stg) * STAGE_B;                                    \
    cp_async16(base + 0 * TILE_B + s0, Ahi + gA0 + kk);                      \
    cp_async16(base + 0 * TILE_B + s1, Ahi + gA1 + kk);                      \
    cp_async16(base + 1 * TILE_B + s0, Alo + gA0 + kk);                      \
    cp_async16(base + 1 * TILE_B + s1, Alo + gA1 + kk);                      \
    cp_async16(base + 2 * TILE_B + s0, Bhi + gB0 + kk);                      \
    cp_async16(base + 2 * TILE_B + s1, Bhi + gB1 + kk);                      \
    cp_async16(base + 3 * TILE_B + s0, Blo + gB0 + kk);                      \
    cp_async16(base + 3 * TILE_B + s1, Blo + gB1 + kk);                      \
} while (0)

    float acc[4][4][4];
#pragma unroll
    for (int i = 0; i < 4; i++)
#pragma unroll
        for (int j = 0; j < 4; j++)
#pragma unroll
            for (int q = 0; q < 4; q++) acc[i][j][q] = 0.0f;

    const int l7 = lane & 7, m4 = lane >> 3;
    const unsigned aoff = (wm * 64 + (m4 & 1) * 8 + l7) * ROW_BYTES + (m4 >> 1) * 16;
    const unsigned boff = (wn * 32 + ((m4 & 2) ? 8 : 0) + l7) * ROW_BYTES + (m4 & 1) * 16;

    const int NCH = K / BK;

    LOAD_CHUNK(0, 0); CP_COMMIT();
    LOAD_CHUNK(1, 1); CP_COMMIT();

    for (int c = 0; c < NCH; c++) {
        cp_wait<1>();
        __syncthreads();

        if (c + 2 < NCH) LOAD_CHUNK(c + 2, (c + 2) % NSTAGE);
        CP_COMMIT();

        const unsigned stg = sb + (c % NSTAGE) * STAGE_B;
#pragma unroll
        for (int ks = 0; ks < 2; ks++) {
            const unsigned kb = ks * 32;
            unsigned ah[4][4], al[4][4], bh[2][4], bl[2][4];
#pragma unroll
            for (int mi = 0; mi < 4; mi++) {
                unsigned ad = stg + aoff + mi * (16 * ROW_BYTES) + kb;
                ldm_x4(ad + 0 * TILE_B, ah[mi]);
                ldm_x4(ad + 1 * TILE_B, al[mi]);
            }
#pragma unroll
            for (int ng = 0; ng < 2; ng++) {
                unsigned bd = stg + boff + ng * (16 * ROW_BYTES) + kb;
                ldm_x4(bd + 2 * TILE_B, bh[ng]);
                ldm_x4(bd + 3 * TILE_B, bl[ng]);
            }
#pragma unroll
            for (int mi = 0; mi < 4; mi++)
#pragma unroll
                for (int ni = 0; ni < 4; ni++) {
                    const int ng = ni >> 1, half = (ni & 1) * 2;
                    unsigned bhr[2] = { bh[ng][half], bh[ng][half + 1] };
                    unsigned blr[2] = { bl[ng][half], bl[ng][half + 1] };
                    mma_bf16(acc[mi][ni], ah[mi], bhr);
                    mma_bf16(acc[mi][ni], ah[mi], blr);
                    mma_bf16(acc[mi][ni], al[mi], bhr);
                }
        }
        __syncthreads();
    }

    const int erow = row0 + wm * 64 + (lane >> 2);
    const int ecol = col0 + wn * 32 + (lane & 3) * 2;
#pragma unroll
    for (int mi = 0; mi < 4; mi++)
#pragma unroll
        for (int ni = 0; ni < 4; ni++) {
            float* p0 = C + (size_t)(erow + mi * 16) * N + ecol + ni * 8;
            float* p1 = p0 + 8 * N;
            p0[0] = acc[mi][ni][0]; p0[1] = acc[mi][ni][1];
            p1[0] = acc[mi][ni][2]; p1[1] = acc[mi][ni][3];
        }
#undef LOAD_CHUNK
}

// ---------------------------------------------------------------------------
// Scores MMA: per (b,h) 128x128 tile, K=64 (one shot), bf16x2 split.
// FIXED loader: 1024 segments (128 rows x 8 segs of 16B) per tile.
// ---------------------------------------------------------------------------
#define SROWB  144                 // 64 elems + 8 pad, bytes
#define STILE  (128 * SROWB)       // 18432
#define SC_SMEM (4 * STILE)        // Qh Ql Kh Kl = 73728

__global__ __launch_bounds__(256) void scores_mma(
    const __nv_bfloat16* __restrict__ qhi, const __nv_bfloat16* __restrict__ qlo,
    const __nv_bfloat16* __restrict__ khi, const __nv_bfloat16* __restrict__ klo,
    const int* __restrict__ masks, float* __restrict__ sc)
{
    extern __shared__ char smem[];
    const unsigned sb = smem_u32(smem);

    const int tid = threadIdx.x, lane = tid & 31, wid = tid >> 5;
    const int wm = wid & 1, wn = wid >> 1;
    const int bh = blockIdx.z, b = bh >> 4, h = bh & 15;
    const int q0 = blockIdx.y * 128, k0 = blockIdx.x * 128;

    // load: per tile 1024 segs (128 rows x 8 of 16B); 4 per thread
#pragma unroll
    for (int t = 0; t < 4; t++) {
        int seg = tid + t * 256;
        int row = seg >> 3, s = seg & 7;
        unsigned sa = sb + row * SROWB + s * 16;
        size_t gq = (size_t)(b * SS + q0 + row) * DIMM + h * HD + s * 8;
        size_t gk = (size_t)(b * SS + k0 + row) * DIMM + h * HD + s * 8;
        cp_async16(sa + 0 * STILE, qhi + gq);
        cp_async16(sa + 1 * STILE, qlo + gq);
        cp_async16(sa + 2 * STILE, khi + gk);
        cp_async16(sa + 3 * STILE, klo + gk);
    }
    CP_COMMIT();
    cp_wait<0>();
    __syncthreads();

    float acc[4][4][4];
#pragma unroll
    for (int i = 0; i < 4; i++)
#pragma unroll
        for (int j = 0; j < 4; j++)
#pragma unroll
            for (int q = 0; q < 4; q++) acc[i][j][q] = 0.0f;

    const int l7 = lane & 7, m4 = lane >> 3;
    const unsigned aoff = (wm * 64 + (m4 & 1) * 8 + l7) * SROWB + (m4 >> 1) * 16;
    const unsigned boff = (wn * 32 + ((m4 & 2) ? 8 : 0) + l7) * SROWB + (m4 & 1) * 16;

#pragma unroll
    for (int ks = 0; ks < 4; ks++) {
        const unsigned kb = ks * 32;
        unsigned ah[4][4], al[4][4], bhf[2][4], blf[2][4];
#pragma unroll
        for (int mi = 0; mi < 4; mi++) {
            unsigned ad = sb + aoff + mi * (16 * SROWB) + kb;
            ldm_x4(ad + 0 * STILE, ah[mi]);
            ldm_x4(ad + 1 * STILE, al[mi]);
        }
#pragma unroll
        for (int ng = 0; ng < 2; ng++) {
            unsigned bd = sb + boff + ng * (16 * SROWB) + kb;
            ldm_x4(bd + 2 * STILE, bhf[ng]);
            ldm_x4(bd + 3 * STILE, blf[ng]);
        }
#pragma unroll
        for (int mi = 0; mi < 4; mi++)
#pragma unroll
            for (int ni = 0; ni < 4; ni++) {
                const int ng = ni >> 1, half = (ni & 1) * 2;
                unsigned bhr[2] = { bhf[ng][half], bhf[ng][half + 1] };
                unsigned blr[2] = { blf[ng][half], blf[ng][half + 1] };
                mma_bf16(acc[mi][ni], ah[mi], bhr);
                mma_bf16(acc[mi][ni], ah[mi], blr);
                mma_bf16(acc[mi][ni], al[mi], bhr);
            }
    }

    const int erow = q0 + wm * 64 + (lane >> 2);
    const int ecol = k0 + wn * 32 + (lane & 3) * 2;
    const float scale = 0.125f;
#pragma unroll
    for (int mi = 0; mi < 4; mi++)
#pragma unroll
        for (int ni = 0; ni < 4; ni++) {
            int r0 = erow + mi * 16, c = ecol + ni * 8;
            const int* mp0 = masks + (size_t)b * SS * SS + (size_t)r0 * SS + c;
            const int* mp1 = mp0 + 8 * SS;
            int2 m0 = *(const int2*)mp0;
            int2 m1 = *(const int2*)mp1;
            float* p0 = sc + ((size_t)bh * SS + r0) * SS + c;
            float* p1 = p0 + 8 * SS;
            float2 o0, o1;
            o0.x = m0.x ? acc[mi][ni][0] * scale : NEG_INF_F;
            o0.y = m0.y ? acc[mi][ni][1] * scale : NEG_INF_F;
            o1.x = m1.x ? acc[mi][ni][2] * scale : NEG_INF_F;
            o1.y = m1.y ? acc[mi][ni][3] * scale : NEG_INF_F;
            *(float2*)p0 = o0;
            *(float2*)p1 = o1;
        }
}

// ---------------------------------------------------------------------------
// Row softmax over 1024 elems; outputs bf16 hi/lo prob arrays.
// ---------------------------------------------------------------------------
__global__ __launch_bounds__(256) void softmax_kernel(const float* __restrict__ sc,
                                                      __nv_bfloat16* __restrict__ phi,
                                                      __nv_bfloat16* __restrict__ plo)
{
    const int row = blockIdx.x;
    const float4* p = (const float4*)(sc + (size_t)row * SS);
    const int tid = threadIdx.x;
    const int lane = tid & 31, w = tid >> 5;

    __shared__ float redm[8];
    __shared__ float reds[8];

    float4 v = p[tid];
    float mx = fmaxf(fmaxf(v.x, v.y), fmaxf(v.z, v.w));
#pragma unroll
    for (int o = 16; o > 0; o >>= 1) mx = fmaxf(mx, __shfl_xor_sync(0xffffffffu, mx, o));
    if (lane == 0) redm[w] = mx;
    __syncthreads();
    float M = redm[0];
#pragma unroll
    for (int i = 1; i < 8; i++) M = fmaxf(M, redm[i]);

    float e0 = __expf(v.x - M);
    float e1 = __expf(v.y - M);
    float e2 = __expf(v.z - M);
    float e3 = __expf(v.w - M);
    float s = e0 + e1 + e2 + e3;
#pragma unroll
    for (int o = 16; o > 0; o >>= 1) s += __shfl_xor_sync(0xffffffffu, s, o);
    if (lane == 0) reds[w] = s;
    __syncthreads();
    float total = 0.0f;
#pragma unroll
    for (int i = 0; i < 8; i++) total += reds[i];
    float inv = 1.0f / total;

    float f0 = e0 * inv, f1 = e1 * inv, f2 = e2 * inv, f3 = e3 * inv;
    __nv_bfloat16 h0 = __float2bfloat16_rn(f0), h1 = __float2bfloat16_rn(f1);
    __nv_bfloat16 h2 = __float2bfloat16_rn(f2), h3 = __float2bfloat16_rn(f3);
    __nv_bfloat16 l0 = __float2bfloat16_rn(f0 - __bfloat162float(h0));
    __nv_bfloat16 l1 = __float2bfloat16_rn(f1 - __bfloat162float(h1));
    __nv_bfloat16 l2 = __float2bfloat16_rn(f2 - __bfloat162float(h2));
    __nv_bfloat16 l3 = __float2bfloat16_rn(f3 - __bfloat162float(h3));
    unsigned hw0 = (unsigned)__bfloat16_as_ushort(h0) | ((unsigned)__bfloat16_as_ushort(h1) << 16);
    unsigned hw1 = (unsigned)__bfloat16_as_ushort(h2) | ((unsigned)__bfloat16_as_ushort(h3) << 16);
    unsigned lw0 = (unsigned)__bfloat16_as_ushort(l0) | ((unsigned)__bfloat16_as_ushort(l1) << 16);
    unsigned lw1 = (unsigned)__bfloat16_as_ushort(l2) | ((unsigned)__bfloat16_as_ushort(l3) << 16);
    ((uint2*)(phi + (size_t)row * SS))[tid] = make_uint2(hw0, hw1);
    ((uint2*)(plo + (size_t)row * SS))[tid] = make_uint2(lw0, lw1);
}

// ---------------------------------------------------------------------------
// PV MMA: per (b,h) ao-tile 128(q) x 64(d), K=1024, 3-stage pipeline.
// ---------------------------------------------------------------------------
#define PV_ATILE  (128 * ROW_BYTES)
#define PV_BTILE  (64  * ROW_BYTES)
#define PV_STAGE  (2 * PV_ATILE + 2 * PV_BTILE)
#define PV_SMEM   (NSTAGE * PV_STAGE)

__global__ __launch_bounds__(256) void pv_mma(
    const __nv_bfloat16* __restrict__ phi, const __nv_bfloat16* __restrict__ plo,
    const __nv_bfloat16* __restrict__ vThi, const __nv_bfloat16* __restrict__ vTlo,
    float* __restrict__ ao)
{
    extern __shared__ char smem[];
    const unsigned sb = smem_u32(smem);

    const int tid = threadIdx.x, lane = tid & 31, wid = tid >> 5;
    const int wm = wid & 3, wn = wid >> 2;
    const int bh = blockIdx.y, b = bh >> 4, h = bh & 15;
    const int q0 = blockIdx.x * 128;

    const __nv_bfloat16* Ph = phi + (size_t)bh * SS * SS;
    const __nv_bfloat16* Pl = plo + (size_t)bh * SS * SS;
    const __nv_bfloat16* Vh = vThi + (size_t)bh * HD * SS;
    const __nv_bfloat16* Vl = vTlo + (size_t)bh * HD * SS;

    const int a0r = tid >> 2, a0s = tid & 3;
    const int a1r = a0r + 64;
    const size_t gA0 = (size_t)(q0 + a0r) * SS + a0s * 8;
    const size_t gA1 = (size_t)(q0 + a1r) * SS + a0s * 8;
    const size_t gB0 = (size_t)a0r * SS + a0s * 8;
    const unsigned sA0 = a0r * ROW_BYTES + a0s * 16;
    const unsigned sA1 = a1r * ROW_BYTES + a0s * 16;
    const unsigned sB0 = a0r * ROW_BYTES + a0s * 16;
    const bool bload = a0r < 64;

#define PV_LOAD(c, stg) do {                                                 \
    const int kk = (c) * BK;                                                 \
    unsigned base = sb + (stg) * PV_STAGE;                                   \
    cp_async16(base + sA0,                 Ph + gA0 + kk);                   \
    cp_async16(base + sA1,                 Ph + gA1 + kk);                   \
    cp_async16(base + PV_ATILE + sA0,      Pl + gA0 + kk);                   \
    cp_async16(base + PV_ATILE + sA1,      Pl + gA1 + kk);                   \
    if (bload) {                                                             \
        cp_async16(base + 2 * PV_ATILE + sB0,            Vh + gB0 + kk);     \
        cp_async16(base + 2 * PV_ATILE + PV_BTILE + sB0, Vl + gB0 + kk);     \
    }                                                                        \
} while (0)

    float acc[2][4][4];
#pragma unroll
    for (int i = 0; i < 2; i++)
#pragma unroll
        for (int j = 0; j < 4; j++)
#pragma unroll
            for (int q = 0; q < 4; q++) acc[i][j][q] = 0.0f;

    const int l7 = lane & 7, m4 = lane >> 3;
    const unsigned aoff = (wm * 32 + (m4 & 1) * 8 + l7) * ROW_BYTES + (m4 >> 1) * 16;
    const unsigned boff = (wn * 32 + ((m4 & 2) ? 8 : 0) + l7) * ROW_BYTES + (m4 & 1) * 16;

    const int NCH = SS / BK;   // 32

    PV_LOAD(0, 0); CP_COMMIT();
    PV_LOAD(1, 1); CP_COMMIT();

    for (int c = 0; c < NCH; c++) {
        cp_wait<1>();
        __syncthreads();

        if (c + 2 < NCH) PV_LOAD(c + 2, (c + 2) % NSTAGE);
        CP_COMMIT();

        const unsigned stg = sb + (c % NSTAGE) * PV_STAGE;
#pragma unroll
        for (int ks = 0; ks < 2; ks++) {
            const unsigned kb = ks * 32;
            unsigned ah[2][4], al[2][4], bhf[2][4], blf[2][4];
#pragma unroll
            for (int mi = 0; mi < 2; mi++) {
                unsigned ad = stg + aoff + mi * (16 * ROW_BYTES) + kb;
                ldm_x4(ad, ah[mi]);
                ldm_x4(ad + PV_ATILE, al[mi]);
            }
#pragma unroll
            for (int ng = 0; ng < 2; ng++) {
                unsigned bd = stg + 2 * PV_ATILE + boff + ng * (16 * ROW_BYTES) + kb;
                ldm_x4(bd, bhf[ng]);
                ldm_x4(bd + PV_BTILE, blf[ng]);
            }
#pragma unroll
            for (int mi = 0; mi < 2; mi++)
#pragma unroll
                for (int ni = 0; ni < 4; ni++) {
                    const int ng = ni >> 1, half = (ni & 1) * 2;
                    unsigned bhr[2] = { bhf[ng][half], bhf[ng][half + 1] };
                    unsigned blr[2] = { blf[ng][half], blf[ng][half + 1] };
                    mma_bf16(acc[mi][ni], ah[mi], bhr);
                    mma_bf16(acc[mi][ni], ah[mi], blr);
                    mma_bf16(acc[mi][ni], al[mi], bhr);
                }
        }
        __syncthreads();
    }

    const int erow = q0 + wm * 32 + (lane >> 2);
    const int ecol = wn * 32 + (lane & 3) * 2;
#pragma unroll
    for (int mi = 0; mi < 2; mi++)
#pragma unroll
        for (int ni = 0; ni < 4; ni++) {
            float* p0 = ao + (size_t)(b * SS + erow + mi * 16) * DIMM + h * HD + ecol + ni * 8;
            float* p1 = p0 + 8 * DIMM;
            p0[0] = acc[mi][ni][0]; p0[1] = acc[mi][ni][1];
            p1[0] = acc[mi][ni][2]; p1[1] = acc[mi][ni][3];
        }
#undef PV_LOAD
}

// ---------------------------------------------------------------------------
// RoPE instruction kernel (unchanged)
// ---------------------------------------------------------------------------
#define ROT(xx, yy, c, s) { float _t = (xx)*(c) - (yy)*(s); (yy) = (xx)*(s) + (yy)*(c); (xx) = _t; }

__global__ __launch_bounds__(256) void rope_kernel(float* __restrict__ q,
                                                   float* __restrict__ k,
                                                   const int* __restrict__ Hm,
                                                   const int* __restrict__ Bm,
                                                   const float* __restrict__ fc,
                                                   const float* __restrict__ fs)
{
    const int tok = blockIdx.x;
    const int tid = threadIdx.x;
    const int h = tid >> 4;
    const int m = tid & 15;
    const int base = tok * DIMM + h * HD;

    float2 qab = *(const float2*)&q[base + 2 * m];
    float2 qcd = *(const float2*)&q[base + 2 * m + 32];
    float2 kab = *(const float2*)&k[base + 2 * m];
    float2 kcd = *(const float2*)&k[base + 2 * m + 32];

    const float cH0 = fc[32 + m],      sH0 = fs[32 + m];
    const float cH1 = fc[32 + m + 16], sH1 = fs[32 + m + 16];
    const float cB0a = fc[32 + 2 * m],     sB0a = fs[32 + 2 * m];
    const float cB0b = fc[32 + 2 * m + 1], sB0b = fs[32 + 2 * m + 1];
    const float cB1a = fc[64 + 2 * m],     sB1a = fs[64 + 2 * m];
    const float cB1b = fc[64 + 2 * m + 1], sB1b = fs[64 + 2 * m + 1];

#pragma unroll
    for (int i = 0; i < 6; i++) {
        if (Hm[i * BS + tok]) {
            ROT(qab.x, qab.y, cH0, sH0); ROT(qcd.x, qcd.y, cH1, sH1);
            ROT(kab.x, kab.y, cH0, sH0); ROT(kcd.x, kcd.y, cH1, sH1);
        }
        if (Bm[(i * 2 + 0) * BS + tok]) {
            ROT(qab.x, qcd.x, cB0a, sB0a); ROT(qab.y, qcd.y, cB0b, sB0b);
            ROT(kab.x, kcd.x, cB0a, sB0a); ROT(kab.y, kcd.y, cB0b, sB0b);
        }
        if (Bm[(i * 2 + 1) * BS + tok]) {
            ROT(qab.x, qcd.x, cB1a, sB1a); ROT(qab.y, qcd.y, cB1b, sB1b);
            ROT(kab.x, kcd.x, cB1a, sB1a); ROT(kab.y, kcd.y, cB1b, sB1b);
        }
    }

    *(float2*)&q[base + 2 * m]      = qab;
    *(float2*)&q[base + 2 * m + 32] = qcd;
    *(float2*)&k[base + 2 * m]      = kab;
    *(float2*)&k[base + 2 * m + 32] = kcd;
}

// ---------------------------------------------------------------------------
extern "C" void kernel_launch(void* const* d_in, const int* in_sizes, int n_in,
                              void* d_out, int out_size)
{
    const float* x     = (const float*)d_in[0];
    const int*   masks = (const int*)d_in[1];
    const int*   Hm    = (const int*)d_in[2];
    const int*   Bm    = (const int*)d_in[3];
    const float* fc    = (const float*)d_in[4];
    const float* fs    = (const float*)d_in[5];
    const float* wq    = (const float*)d_in[6];
    const float* wk    = (const float*)d_in[7];
    const float* wv    = (const float*)d_in[8];
    const float* wo    = (const float*)d_in[9];
    float* out = (float*)d_out;

    float *gq, *gk, *gv, *gao, *gsc;
    __nv_bfloat16 *xhi, *xlo, *aohi, *aolo, *whi, *wlo;
    __nv_bfloat16 *qhi, *qlo, *khi, *klo, *vThi, *vTlo, *phi, *plo;
    cudaGetSymbolAddress((void**)&gq,   g_q);
    cudaGetSymbolAddress((void**)&gk,   g_k);
    cudaGetSymbolAddress((void**)&gv,   g_v);
    cudaGetSymbolAddress((void**)&gao,  g_ao);
    cudaGetSymbolAddress((void**)&gsc,  g_sc);
    cudaGetSymbolAddress((void**)&xhi,  g_xhi);
    cudaGetSymbolAddress((void**)&xlo,  g_xlo);
    cudaGetSymbolAddress((void**)&aohi, g_aohi);
    cudaGetSymbolAddress((void**)&aolo, g_aolo);
    cudaGetSymbolAddress((void**)&whi,  g_whi);
    cudaGetSymbolAddress((void**)&wlo,  g_wlo);
    cudaGetSymbolAddress((void**)&qhi,  g_qhi);
    cudaGetSymbolAddress((void**)&qlo,  g_qlo);
    cudaGetSymbolAddress((void**)&khi,  g_khi);
    cudaGetSymbolAddress((void**)&klo,  g_klo);
    cudaGetSymbolAddress((void**)&vThi, g_vThi);
    cudaGetSymbolAddress((void**)&vTlo, g_vTlo);
    cudaGetSymbolAddress((void**)&phi,  g_phi);
    cudaGetSymbolAddress((void**)&plo,  g_plo);

    static bool attr_done = false;
    if (!attr_done) {
        cudaFuncSetAttribute(gemm_mma,   cudaFuncAttributeMaxDynamicSharedMemorySize, GEMM_SMEM);
        cudaFuncSetAttribute(scores_mma, cudaFuncAttributeMaxDynamicSharedMemorySize, SC_SMEM);
        cudaFuncSetAttribute(pv_mma,     cudaFuncAttributeMaxDynamicSharedMemorySize, PV_SMEM);
        attr_done = true;
    }

    const size_t WSZ = (size_t)DIMM * DIMM;
    dim3 gPrep(32, 32);
    prep_w<<<gPrep, 256>>>(wq, whi + 0 * WSZ, wlo + 0 * WSZ);
    prep_w<<<gPrep, 256>>>(wk, whi + 1 * WSZ, wlo + 1 * WSZ);
    prep_w<<<gPrep, 256>>>(wv, whi + 2 * WSZ, wlo + 2 * WSZ);
    prep_w<<<gPrep, 256>>>(wo, whi + 3 * WSZ, wlo + 3 * WSZ);

    split_f32<<<BS * DIMM / 4 / 256, 256>>>((const float4*)x, xhi, xlo);

    dim3 gGemm(DIMM / 128, BS / 128);
    gemm_mma<<<gGemm, 256, GEMM_SMEM>>>(xhi, xlo, whi + 0 * WSZ, wlo + 0 * WSZ, gq, BS, DIMM, DIMM);
    gemm_mma<<<gGemm, 256, GEMM_SMEM>>>(xhi, xlo, whi + 1 * WSZ, wlo + 1 * WSZ, gk, BS, DIMM, DIMM);
    gemm_mma<<<gGemm, 256, GEMM_SMEM>>>(xhi, xlo, whi + 2 * WSZ, wlo + 2 * WSZ, gv, BS, DIMM, DIMM);

    rope_kernel<<<BS, 256>>>(gq, gk, Hm, Bm, fc, fs);

    split_f32<<<BS * DIMM / 4 / 256, 256>>>((const float4*)gq, qhi, qlo);
    split_f32<<<BS * DIMM / 4 / 256, 256>>>((const float4*)gk, khi, klo);
    vt_split<<<dim3(SS / 32, HD / 32, BB * NH), 256>>>(gv, vThi, vTlo);

    scores_mma<<<dim3(SS / 128, SS / 128, BB * NH), 256, SC_SMEM>>>(qhi, qlo, khi, klo, masks, gsc);
    softmax_kernel<<<BB * NH * SS, 256>>>(gsc, phi, plo);
    pv_mma<<<dim3(SS / 128, BB * NH), 256, PV_SMEM>>>(phi, plo, vThi, vTlo, gao);

    split_f32<<<BS * DIMM / 4 / 256, 256>>>((const float4*)gao, aohi, aolo);
    gemm_mma<<<gGemm, 256, GEMM_SMEM>>>(aohi, aolo, whi + 3 * WSZ, wlo + 3 * WSZ, out, BS, DIMM, DIMM);
}

// round 6
// speedup vs baseline: 3.1932x; 1.2163x over previous
#include <cuda_runtime.h>
#include <cuda_bf16.h>

// Problem constants
#define BB   2
#define SS   1024
#define DIMM 1024
#define NH   16
#define HD   64
#define BS   (BB * SS)
#define NEG_INF_F (-1000000000.0f)

// ---------------------------------------------------------------------------
// Scratch (static device globals; no allocation anywhere)
// ---------------------------------------------------------------------------
__device__ float g_q [BS * DIMM];
__device__ float g_k [BS * DIMM];
__device__ float g_v [BS * DIMM];
__device__ __nv_bfloat16 g_xhi [BS * DIMM];
__device__ __nv_bfloat16 g_xlo [BS * DIMM];
__device__ __nv_bfloat16 g_aohi[BS * DIMM];
__device__ __nv_bfloat16 g_aolo[BS * DIMM];
__device__ __nv_bfloat16 g_whi [4 * DIMM * DIMM];  // transposed [n][k]
__device__ __nv_bfloat16 g_wlo [4 * DIMM * DIMM];
__device__ __nv_bfloat16 g_qhi [BS * DIMM];
__device__ __nv_bfloat16 g_qlo [BS * DIMM];
__device__ __nv_bfloat16 g_khi [BS * DIMM];
__device__ __nv_bfloat16 g_klo [BS * DIMM];
__device__ __nv_bfloat16 g_vhi [BS * DIMM];
__device__ __nv_bfloat16 g_vlo [BS * DIMM];

// ---------------------------------------------------------------------------
// PTX helpers (baseline ISA only)
// ---------------------------------------------------------------------------
__device__ __forceinline__ unsigned smem_u32(const void* p) {
    unsigned a;
    asm("{ .reg .u64 t; cvta.to.shared.u64 t, %1; cvt.u32.u64 %0, t; }"
        : "=r"(a) : "l"(p));
    return a;
}

__device__ __forceinline__ void cp_async16(unsigned saddr, const void* gaddr) {
    asm volatile("cp.async.cg.shared.global [%0], [%1], 16;"
                 :: "r"(saddr), "l"(gaddr));
}
#define CP_COMMIT() asm volatile("cp.async.commit_group;")
template <int N>
__device__ __forceinline__ void cp_wait() {
    asm volatile("cp.async.wait_group %0;" :: "n"(N));
}

__device__ __forceinline__ void ldm_x4(unsigned addr, unsigned* r) {
    asm volatile("ldmatrix.sync.aligned.m8n8.x4.shared.b16 {%0,%1,%2,%3}, [%4];"
                 : "=r"(r[0]), "=r"(r[1]), "=r"(r[2]), "=r"(r[3]) : "r"(addr));
}

__device__ __forceinline__ void ldm_x4_t(unsigned addr, unsigned* r) {
    asm volatile("ldmatrix.sync.aligned.m8n8.x4.trans.shared.b16 {%0,%1,%2,%3}, [%4];"
                 : "=r"(r[0]), "=r"(r[1]), "=r"(r[2]), "=r"(r[3]) : "r"(addr));
}

__device__ __forceinline__ void mma_bf16(float* c, const unsigned* a,
                                         const unsigned* b) {
    asm volatile(
        "mma.sync.aligned.m16n8k16.row.col.f32.bf16.bf16.f32 "
        "{%0,%1,%2,%3}, {%4,%5,%6,%7}, {%8,%9}, {%0,%1,%2,%3};"
        : "+f"(c[0]), "+f"(c[1]), "+f"(c[2]), "+f"(c[3])
        : "r"(a[0]), "r"(a[1]), "r"(a[2]), "r"(a[3]), "r"(b[0]), "r"(b[1]));
}

__device__ __forceinline__ unsigned pk2(float x, float y) {
    __nv_bfloat162 t = __floats2bfloat162_rn(x, y);
    return *(unsigned*)&t;
}

// ---------------------------------------------------------------------------
// Weight prep: fp32 w[k][n] -> bf16 hi/lo [n][k] (transposed, split)
// ---------------------------------------------------------------------------
__global__ __launch_bounds__(256) void prep_w(const float* __restrict__ w,
                                              __nv_bfloat16* __restrict__ hi,
                                              __nv_bfloat16* __restrict__ lo)
{
    __shared__ float t[32][33];
    const int tx = threadIdx.x & 31, ty = threadIdx.x >> 5;
    const int n0 = blockIdx.x * 32, k0 = blockIdx.y * 32;
#pragma unroll
    for (int i = 0; i < 4; i++)
        t[ty + 8 * i][tx] = w[(size_t)(k0 + ty + 8 * i) * DIMM + n0 + tx];
    __syncthreads();
#pragma unroll
    for (int i = 0; i < 4; i++) {
        float v = t[tx][ty + 8 * i];
        __nv_bfloat16 h = __float2bfloat16_rn(v);
        float r = v - __bfloat162float(h);
        size_t o = (size_t)(n0 + ty + 8 * i) * DIMM + k0 + tx;
        hi[o] = h;
        lo[o] = __float2bfloat16_rn(r);
    }
}

// ---------------------------------------------------------------------------
// Activation split: fp32 -> bf16 hi/lo
// ---------------------------------------------------------------------------
__global__ __launch_bounds__(256) void split_f32(const float4* __restrict__ in,
                                                 __nv_bfloat16* __restrict__ hi,
                                                 __nv_bfloat16* __restrict__ lo)
{
    const int i = blockIdx.x * 256 + threadIdx.x;
    float4 v = in[i];
    __nv_bfloat16 h0 = __float2bfloat16_rn(v.x), h1 = __float2bfloat16_rn(v.y);
    __nv_bfloat16 h2 = __float2bfloat16_rn(v.z), h3 = __float2bfloat16_rn(v.w);
    __nv_bfloat16 l0 = __float2bfloat16_rn(v.x - __bfloat162float(h0));
    __nv_bfloat16 l1 = __float2bfloat16_rn(v.y - __bfloat162float(h1));
    __nv_bfloat16 l2 = __float2bfloat16_rn(v.z - __bfloat162float(h2));
    __nv_bfloat16 l3 = __float2bfloat16_rn(v.w - __bfloat162float(h3));
    unsigned hw0 = (unsigned)__bfloat16_as_ushort(h0) | ((unsigned)__bfloat16_as_ushort(h1) << 16);
    unsigned hw1 = (unsigned)__bfloat16_as_ushort(h2) | ((unsigned)__bfloat16_as_ushort(h3) << 16);
    unsigned lw0 = (unsigned)__bfloat16_as_ushort(l0) | ((unsigned)__bfloat16_as_ushort(l1) << 16);
    unsigned lw1 = (unsigned)__bfloat16_as_ushort(l2) | ((unsigned)__bfloat16_as_ushort(l3) << 16);
    ((uint2*)hi)[i] = make_uint2(hw0, hw1);
    ((uint2*)lo)[i] = make_uint2(lw0, lw1);
}

// ---------------------------------------------------------------------------
// MMA GEMM core (128x128 tile, BK=32, 3-stage). Used for QKV (fused, grid.z)
// and the output projection.
// ---------------------------------------------------------------------------
#define BK        32
#define ROW_ELEMS 40
#define ROW_BYTES (ROW_ELEMS * 2)
#define TILE_B    (128 * ROW_BYTES)
#define STAGE_B   (4 * TILE_B)
#define NSTAGE    3
#define GEMM_SMEM (NSTAGE * STAGE_B)

__device__ __forceinline__ void gemm_body(
    const __nv_bfloat16* __restrict__ Ahi, const __nv_bfloat16* __restrict__ Alo,
    const __nv_bfloat16* __restrict__ Bhi, const __nv_bfloat16* __restrict__ Blo,
    float* __restrict__ C, int M, int N, int K, int row0, int col0)
{
    extern __shared__ char smem[];
    const unsigned sb = smem_u32(smem);

    const int tid  = threadIdx.x;
    const int lane = tid & 31;
    const int wid  = tid >> 5;
    const int wm   = wid & 1;
    const int wn   = wid >> 1;

    const int t0r = tid >> 2, t0s = tid & 3;
    const int t1r = t0r + 64;
    const size_t gA0 = (size_t)(row0 + t0r) * K + t0s * 8;
    const size_t gA1 = (size_t)(row0 + t1r) * K + t0s * 8;
    const size_t gB0 = (size_t)(col0 + t0r) * K + t0s * 8;
    const size_t gB1 = (size_t)(col0 + t1r) * K + t0s * 8;
    const unsigned s0 = t0r * ROW_BYTES + t0s * 16;
    const unsigned s1 = t1r * ROW_BYTES + t0s * 16;

#define LOAD_CHUNK(c, stg) do {                                              \
    const int kk = (c) * BK;                                                 \
    unsigned base = sb + (stg) * STAGE_B;                                    \
    cp_async16(base + 0 * TILE_B + s0, Ahi + gA0 + kk);                      \
    cp_async16(base + 0 * TILE_B + s1, Ahi + gA1 + kk);                      \
    cp_async16(base + 1 * TILE_B + s0, Alo + gA0 + kk);                      \
    cp_async16(base + 1 * TILE_B + s1, Alo + gA1 + kk);                      \
    cp_async16(base + 2 * TILE_B + s0, Bhi + gB0 + kk);                      \
    cp_async16(base + 2 * TILE_B + s1, Bhi + gB1 + kk);                      \
    cp_async16(base + 3 * TILE_B + s0, Blo + gB0 + kk);                      \
    cp_async16(base + 3 * TILE_B + s1, Blo + gB1 + kk);                      \
} while (0)

    float acc[4][4][4];
#pragma unroll
    for (int i = 0; i < 4; i++)
#pragma unroll
        for (int j = 0; j < 4; j++)
#pragma unroll
            for (int q = 0; q < 4; q++) acc[i][j][q] = 0.0f;

    const int l7 = lane & 7, m4 = lane >> 3;
    const unsigned aoff = (wm * 64 + (m4 & 1) * 8 + l7) * ROW_BYTES + (m4 >> 1) * 16;
    const unsigned boff = (wn * 32 + ((m4 & 2) ? 8 : 0) + l7) * ROW_BYTES + (m4 & 1) * 16;

    const int NCH = K / BK;

    LOAD_CHUNK(0, 0); CP_COMMIT();
    LOAD_CHUNK(1, 1); CP_COMMIT();

    for (int c = 0; c < NCH; c++) {
        cp_wait<1>();
        __syncthreads();

        if (c + 2 < NCH) LOAD_CHUNK(c + 2, (c + 2) % NSTAGE);
        CP_COMMIT();

        const unsigned stg = sb + (c % NSTAGE) * STAGE_B;
#pragma unroll
        for (int ks = 0; ks < 2; ks++) {
            const unsigned kb = ks * 32;
            unsigned ah[4][4], al[4][4], bh[2][4], bl[2][4];
#pragma unroll
            for (int mi = 0; mi < 4; mi++) {
                unsigned ad = stg + aoff + mi * (16 * ROW_BYTES) + kb;
                ldm_x4(ad + 0 * TILE_B, ah[mi]);
                ldm_x4(ad + 1 * TILE_B, al[mi]);
            }
#pragma unroll
            for (int ng = 0; ng < 2; ng++) {
                unsigned bd = stg + boff + ng * (16 * ROW_BYTES) + kb;
                ldm_x4(bd + 2 * TILE_B, bh[ng]);
                ldm_x4(bd + 3 * TILE_B, bl[ng]);
            }
#pragma unroll
            for (int mi = 0; mi < 4; mi++)
#pragma unroll
                for (int ni = 0; ni < 4; ni++) {
                    const int ng = ni >> 1, half = (ni & 1) * 2;
                    unsigned bhr[2] = { bh[ng][half], bh[ng][half + 1] };
                    unsigned blr[2] = { bl[ng][half], bl[ng][half + 1] };
                    mma_bf16(acc[mi][ni], ah[mi], bhr);
                    mma_bf16(acc[mi][ni], ah[mi], blr);
                    mma_bf16(acc[mi][ni], al[mi], bhr);
                }
        }
        __syncthreads();
    }

    const int erow = row0 + wm * 64 + (lane >> 2);
    const int ecol = col0 + wn * 32 + (lane & 3) * 2;
#pragma unroll
    for (int mi = 0; mi < 4; mi++)
#pragma unroll
        for (int ni = 0; ni < 4; ni++) {
            float* p0 = C + (size_t)(erow + mi * 16) * N + ecol + ni * 8;
            float* p1 = p0 + 8 * N;
            p0[0] = acc[mi][ni][0]; p0[1] = acc[mi][ni][1];
            p1[0] = acc[mi][ni][2]; p1[1] = acc[mi][ni][3];
        }
#undef LOAD_CHUNK
}

__global__ __launch_bounds__(256) void gemm_mma(
    const __nv_bfloat16* __restrict__ Ahi, const __nv_bfloat16* __restrict__ Alo,
    const __nv_bfloat16* __restrict__ Bhi, const __nv_bfloat16* __restrict__ Blo,
    float* __restrict__ C, int M, int N, int K)
{
    gemm_body(Ahi, Alo, Bhi, Blo, C, M, N, K, blockIdx.y * 128, blockIdx.x * 128);
}

// Fused QKV: grid.z selects weight slice + destination.
__global__ __launch_bounds__(256) void gemm_qkv(
    const __nv_bfloat16* __restrict__ Ahi, const __nv_bfloat16* __restrict__ Alo,
    const __nv_bfloat16* __restrict__ Whi, const __nv_bfloat16* __restrict__ Wlo,
    float* __restrict__ Cq, float* __restrict__ Ck, float* __restrict__ Cv)
{
    const size_t WSZ = (size_t)DIMM * DIMM;
    const int z = blockIdx.z;
    const __nv_bfloat16* Bhi = Whi + (size_t)z * WSZ;
    const __nv_bfloat16* Blo = Wlo + (size_t)z * WSZ;
    float* C = (z == 0) ? Cq : (z == 1) ? Ck : Cv;
    gemm_body(Ahi, Alo, Bhi, Blo, C, BS, DIMM, DIMM, blockIdx.y * 128, blockIdx.x * 128);
}

// ---------------------------------------------------------------------------
// Flash attention: per (b,h,q-tile 128) CTA; 8 warps x 16 q-rows (full width).
// Online softmax in registers; K/V double-buffered cp.async; V via ldmatrix.trans.
// Writes ao directly as bf16 hi/lo.
// ---------------------------------------------------------------------------
#define FROWB  144
#define FTILE  (128 * FROWB)          // 18432
#define FSTAGE (4 * FTILE)            // Kh, Kl, Vh, Vl
#define FLASH_SMEM (2 * FTILE + 2 * FSTAGE)   // 184320

__global__ __launch_bounds__(256, 1) void flash_mma(
    const __nv_bfloat16* __restrict__ qhi, const __nv_bfloat16* __restrict__ qlo,
    const __nv_bfloat16* __restrict__ khi, const __nv_bfloat16* __restrict__ klo,
    const __nv_bfloat16* __restrict__ vhi, const __nv_bfloat16* __restrict__ vlo,
    const int* __restrict__ masks,
    __nv_bfloat16* __restrict__ aohi, __nv_bfloat16* __restrict__ aolo)
{
    extern __shared__ char smem[];
    const unsigned sb = smem_u32(smem);
    const int tid = threadIdx.x, lane = tid & 31, wid = tid >> 5;
    const int bh = blockIdx.y, b = bh >> 4, h = bh & 15;
    const int q0 = blockIdx.x * 128;
    const int wq0 = wid * 16;

    const unsigned sQh = sb, sQl = sb + FTILE;

    // Q load: 2 tiles x 1024 segs
#pragma unroll
    for (int t = 0; t < 4; t++) {
        int seg = tid + t * 256, row = seg >> 3, s = seg & 7;
        size_t g = (size_t)(b * SS + q0 + row) * DIMM + h * HD + s * 8;
        unsigned sa = row * FROWB + s * 16;
        cp_async16(sQh + sa, qhi + g);
        cp_async16(sQl + sa, qlo + g);
    }

#define KV_LOAD(kt, stg) do {                                                \
    unsigned base = sb + 2 * FTILE + (stg) * FSTAGE;                         \
    _Pragma("unroll")                                                        \
    for (int t = 0; t < 4; t++) {                                            \
        int seg = tid + t * 256, row = seg >> 3, s = seg & 7;                \
        size_t g = (size_t)(b * SS + (kt) * 128 + row) * DIMM + h * HD + s * 8; \
        unsigned sa = row * FROWB + s * 16;                                  \
        cp_async16(base + sa,             khi + g);                          \
        cp_async16(base + FTILE + sa,     klo + g);                          \
        cp_async16(base + 2 * FTILE + sa, vhi + g);                          \
        cp_async16(base + 3 * FTILE + sa, vlo + g);                          \
    }                                                                        \
} while (0)

    KV_LOAD(0, 0); CP_COMMIT();
    KV_LOAD(1, 1); CP_COMMIT();

    float m0 = -1e30f, m1 = -1e30f, l0 = 0.0f, l1 = 0.0f;
    float acc_o[8][4];
#pragma unroll
    for (int j = 0; j < 8; j++)
#pragma unroll
        for (int q = 0; q < 4; q++) acc_o[j][q] = 0.0f;

    const int l7 = lane & 7, m4 = lane >> 3;
    const unsigned qoff = (wq0 + (m4 & 1) * 8 + l7) * FROWB + (m4 >> 1) * 16;
    const unsigned koff = (((m4 & 2) ? 8 : 0) + l7) * FROWB + (m4 & 1) * 16;
    const unsigned voff = (lane & 15) * FROWB + (lane >> 4) * 16;

    const int gr0 = q0 + wq0 + (lane >> 2);
    const int* mrow0 = masks + (size_t)b * SS * SS + (size_t)gr0 * SS;
    const int* mrow1 = mrow0 + 8 * SS;

    for (int kt = 0; kt < 8; kt++) {
        if (kt == 7) cp_wait<0>(); else cp_wait<1>();
        __syncthreads();
        const unsigned kbase = sb + 2 * FTILE + (kt & 1) * FSTAGE;

        // ---- S = Q K^T (3-pass split) ----
        float s[16][4];
#pragma unroll
        for (int ni = 0; ni < 16; ni++)
#pragma unroll
            for (int q = 0; q < 4; q++) s[ni][q] = 0.0f;

#pragma unroll
        for (int ks = 0; ks < 4; ks++) {
            unsigned ah[4], al[4];
            ldm_x4(sQh + qoff + ks * 32, ah);
            ldm_x4(sQl + qoff + ks * 32, al);
#pragma unroll
            for (int g = 0; g < 8; g++) {
                unsigned bh4[4], bl4[4];
                unsigned ba = kbase + koff + g * (16 * FROWB) + ks * 32;
                ldm_x4(ba, bh4);
                ldm_x4(ba + FTILE, bl4);
                unsigned bh0[2] = { bh4[0], bh4[1] }, bh1[2] = { bh4[2], bh4[3] };
                unsigned bl0[2] = { bl4[0], bl4[1] }, bl1[2] = { bl4[2], bl4[3] };
                mma_bf16(s[2 * g],     ah, bh0); mma_bf16(s[2 * g],     ah, bl0); mma_bf16(s[2 * g],     al, bh0);
                mma_bf16(s[2 * g + 1], ah, bh1); mma_bf16(s[2 * g + 1], ah, bl1); mma_bf16(s[2 * g + 1], al, bh1);
            }
        }

        // ---- mask + scale ----
        const int kc0 = kt * 128 + (lane & 3) * 2;
#pragma unroll
        for (int ni = 0; ni < 16; ni++) {
            int2 mk0 = *(const int2*)(mrow0 + kc0 + ni * 8);
            int2 mk1 = *(const int2*)(mrow1 + kc0 + ni * 8);
            s[ni][0] = mk0.x ? s[ni][0] * 0.125f : NEG_INF_F;
            s[ni][1] = mk0.y ? s[ni][1] * 0.125f : NEG_INF_F;
            s[ni][2] = mk1.x ? s[ni][2] * 0.125f : NEG_INF_F;
            s[ni][3] = mk1.y ? s[ni][3] * 0.125f : NEG_INF_F;
        }

        // ---- online softmax ----
        float mx0 = -1e30f, mx1 = -1e30f;
#pragma unroll
        for (int ni = 0; ni < 16; ni++) {
            mx0 = fmaxf(mx0, fmaxf(s[ni][0], s[ni][1]));
            mx1 = fmaxf(mx1, fmaxf(s[ni][2], s[ni][3]));
        }
        mx0 = fmaxf(mx0, __shfl_xor_sync(0xffffffffu, mx0, 1));
        mx0 = fmaxf(mx0, __shfl_xor_sync(0xffffffffu, mx0, 2));
        mx1 = fmaxf(mx1, __shfl_xor_sync(0xffffffffu, mx1, 1));
        mx1 = fmaxf(mx1, __shfl_xor_sync(0xffffffffu, mx1, 2));

        float mn0 = fmaxf(m0, mx0), mn1 = fmaxf(m1, mx1);
        float al0 = __expf(m0 - mn0), al1 = __expf(m1 - mn1);
        m0 = mn0; m1 = mn1;

        float sum0 = 0.0f, sum1 = 0.0f;
#pragma unroll
        for (int ni = 0; ni < 16; ni++) {
            s[ni][0] = __expf(s[ni][0] - mn0);
            s[ni][1] = __expf(s[ni][1] - mn0);
            s[ni][2] = __expf(s[ni][2] - mn1);
            s[ni][3] = __expf(s[ni][3] - mn1);
            sum0 += s[ni][0] + s[ni][1];
            sum1 += s[ni][2] + s[ni][3];
        }
        sum0 += __shfl_xor_sync(0xffffffffu, sum0, 1);
        sum0 += __shfl_xor_sync(0xffffffffu, sum0, 2);
        sum1 += __shfl_xor_sync(0xffffffffu, sum1, 1);
        sum1 += __shfl_xor_sync(0xffffffffu, sum1, 2);
        l0 = l0 * al0 + sum0;
        l1 = l1 * al1 + sum1;

#pragma unroll
        for (int j = 0; j < 8; j++) {
            acc_o[j][0] *= al0; acc_o[j][1] *= al0;
            acc_o[j][2] *= al1; acc_o[j][3] *= al1;
        }

        // ---- O += P V (3-pass split; P repacked C->A fragment) ----
#pragma unroll
        for (int kc = 0; kc < 8; kc++) {
            unsigned aH[4], aL[4];
            {
                float p00 = s[2 * kc][0],     p01 = s[2 * kc][1];
                float p10 = s[2 * kc][2],     p11 = s[2 * kc][3];
                float p20 = s[2 * kc + 1][0], p21 = s[2 * kc + 1][1];
                float p30 = s[2 * kc + 1][2], p31 = s[2 * kc + 1][3];
                aH[0] = pk2(p00, p01); aH[1] = pk2(p10, p11);
                aH[2] = pk2(p20, p21); aH[3] = pk2(p30, p31);
                __nv_bfloat162* hp;
                hp = (__nv_bfloat162*)&aH[0];
                aL[0] = pk2(p00 - __bfloat162float(hp->x), p01 - __bfloat162float(hp->y));
                hp = (__nv_bfloat162*)&aH[1];
                aL[1] = pk2(p10 - __bfloat162float(hp->x), p11 - __bfloat162float(hp->y));
                hp = (__nv_bfloat162*)&aH[2];
                aL[2] = pk2(p20 - __bfloat162float(hp->x), p21 - __bfloat162float(hp->y));
                hp = (__nv_bfloat162*)&aH[3];
                aL[3] = pk2(p30 - __bfloat162float(hp->x), p31 - __bfloat162float(hp->y));
            }
#pragma unroll
            for (int dg = 0; dg < 4; dg++) {
                unsigned bh4[4], bl4[4];
                unsigned va = kbase + 2 * FTILE + voff + kc * (16 * FROWB) + dg * 32;
                ldm_x4_t(va, bh4);
                ldm_x4_t(va + FTILE, bl4);
                unsigned b0h[2] = { bh4[0], bh4[1] }, b1h[2] = { bh4[2], bh4[3] };
                unsigned b0l[2] = { bl4[0], bl4[1] }, b1l[2] = { bl4[2], bl4[3] };
                mma_bf16(acc_o[2 * dg],     aH, b0h);
                mma_bf16(acc_o[2 * dg],     aH, b0l);
                mma_bf16(acc_o[2 * dg],     aL, b0h);
                mma_bf16(acc_o[2 * dg + 1], aH, b1h);
                mma_bf16(acc_o[2 * dg + 1], aH, b1l);
                mma_bf16(acc_o[2 * dg + 1], aL, b1h);
            }
        }

        __syncthreads();
        if (kt + 2 < 8) { KV_LOAD(kt + 2, kt & 1); CP_COMMIT(); }
    }

    // ---- epilogue: normalize + split + store ----
    const float inv0 = 1.0f / l0, inv1 = 1.0f / l1;
    const size_t o0 = (size_t)(b * SS + gr0) * DIMM + h * HD + (lane & 3) * 2;
    const size_t o1 = o0 + (size_t)8 * DIMM;
#pragma unroll
    for (int j = 0; j < 8; j++) {
        float v00 = acc_o[j][0] * inv0, v01 = acc_o[j][1] * inv0;
        float v10 = acc_o[j][2] * inv1, v11 = acc_o[j][3] * inv1;
        unsigned h0 = pk2(v00, v01), h1 = pk2(v10, v11);
        __nv_bfloat162* hp;
        hp = (__nv_bfloat162*)&h0;
        unsigned w0 = pk2(v00 - __bfloat162float(hp->x), v01 - __bfloat162float(hp->y));
        hp = (__nv_bfloat162*)&h1;
        unsigned w1 = pk2(v10 - __bfloat162float(hp->x), v11 - __bfloat162float(hp->y));
        *(unsigned*)(aohi + o0 + j * 8) = h0;
        *(unsigned*)(aolo + o0 + j * 8) = w0;
        *(unsigned*)(aohi + o1 + j * 8) = h1;
        *(unsigned*)(aolo + o1 + j * 8) = w1;
    }
#undef KV_LOAD
}

// ---------------------------------------------------------------------------
// RoPE instruction kernel (unchanged)
// ---------------------------------------------------------------------------
#define ROT(xx, yy, c, s) { float _t = (xx)*(c) - (yy)*(s); (yy) = (xx)*(s) + (yy)*(c); (xx) = _t; }

__global__ __launch_bounds__(256) void rope_kernel(float* __restrict__ q,
                                                   float* __restrict__ k,
                                                   const int* __restrict__ Hm,
                                                   const int* __restrict__ Bm,
                                                   const float* __restrict__ fc,
                                                   const float* __restrict__ fs)
{
    const int tok = blockIdx.x;
    const int tid = threadIdx.x;
    const int h = tid >> 4;
    const int m = tid & 15;
    const int base = tok * DIMM + h * HD;

    float2 qab = *(const float2*)&q[base + 2 * m];
    float2 qcd = *(const float2*)&q[base + 2 * m + 32];
    float2 kab = *(const float2*)&k[base + 2 * m];
    float2 kcd = *(const float2*)&k[base + 2 * m + 32];

    const float cH0 = fc[32 + m],      sH0 = fs[32 + m];
    const float cH1 = fc[32 + m + 16], sH1 = fs[32 + m + 16];
    const float cB0a = fc[32 + 2 * m],     sB0a = fs[32 + 2 * m];
    const float cB0b = fc[32 + 2 * m + 1], sB0b = fs[32 + 2 * m + 1];
    const float cB1a = fc[64 + 2 * m],     sB1a = fs[64 + 2 * m];
    const float cB1b = fc[64 + 2 * m + 1], sB1b = fs[64 + 2 * m + 1];

#pragma unroll
    for (int i = 0; i < 6; i++) {
        if (Hm[i * BS + tok]) {
            ROT(qab.x, qab.y, cH0, sH0); ROT(qcd.x, qcd.y, cH1, sH1);
            ROT(kab.x, kab.y, cH0, sH0); ROT(kcd.x, kcd.y, cH1, sH1);
        }
        if (Bm[(i * 2 + 0) * BS + tok]) {
            ROT(qab.x, qcd.x, cB0a, sB0a); ROT(qab.y, qcd.y, cB0b, sB0b);
            ROT(kab.x, kcd.x, cB0a, sB0a); ROT(kab.y, kcd.y, cB0b, sB0b);
        }
        if (Bm[(i * 2 + 1) * BS + tok]) {
            ROT(qab.x, qcd.x, cB1a, sB1a); ROT(qab.y, qcd.y, cB1b, sB1b);
            ROT(kab.x, kcd.x, cB1a, sB1a); ROT(kab.y, kcd.y, cB1b, sB1b);
        }
    }

    *(float2*)&q[base + 2 * m]      = qab;
    *(float2*)&q[base + 2 * m + 32] = qcd;
    *(float2*)&k[base + 2 * m]      = kab;
    *(float2*)&k[base + 2 * m + 32] = kcd;
}

// ---------------------------------------------------------------------------
extern "C" void kernel_launch(void* const* d_in, const int* in_sizes, int n_in,
                              void* d_out, int out_size)
{
    const float* x     = (const float*)d_in[0];
    const int*   masks = (const int*)d_in[1];
    const int*   Hm    = (const int*)d_in[2];
    const int*   Bm    = (const int*)d_in[3];
    const float* fc    = (const float*)d_in[4];
    const float* fs    = (const float*)d_in[5];
    const float* wq    = (const float*)d_in[6];
    const float* wk    = (const float*)d_in[7];
    const float* wv    = (const float*)d_in[8];
    const float* wo    = (const float*)d_in[9];
    float* out = (float*)d_out;

    float *gq, *gk, *gv;
    __nv_bfloat16 *xhi, *xlo, *aohi, *aolo, *whi, *wlo;
    __nv_bfloat16 *qhi, *qlo, *khi, *klo, *vhi, *vlo;
    cudaGetSymbolAddress((void**)&gq,   g_q);
    cudaGetSymbolAddress((void**)&gk,   g_k);
    cudaGetSymbolAddress((void**)&gv,   g_v);
    cudaGetSymbolAddress((void**)&xhi,  g_xhi);
    cudaGetSymbolAddress((void**)&xlo,  g_xlo);
    cudaGetSymbolAddress((void**)&aohi, g_aohi);
    cudaGetSymbolAddress((void**)&aolo, g_aolo);
    cudaGetSymbolAddress((void**)&whi,  g_whi);
    cudaGetSymbolAddress((void**)&wlo,  g_wlo);
    cudaGetSymbolAddress((void**)&qhi,  g_qhi);
    cudaGetSymbolAddress((void**)&qlo,  g_qlo);
    cudaGetSymbolAddress((void**)&khi,  g_khi);
    cudaGetSymbolAddress((void**)&klo,  g_klo);
    cudaGetSymbolAddress((void**)&vhi,  g_vhi);
    cudaGetSymbolAddress((void**)&vlo,  g_vlo);

    static bool attr_done = false;
    if (!attr_done) {
        cudaFuncSetAttribute(gemm_mma,  cudaFuncAttributeMaxDynamicSharedMemorySize, GEMM_SMEM);
        cudaFuncSetAttribute(gemm_qkv,  cudaFuncAttributeMaxDynamicSharedMemorySize, GEMM_SMEM);
        cudaFuncSetAttribute(flash_mma, cudaFuncAttributeMaxDynamicSharedMemorySize, FLASH_SMEM);
        attr_done = true;
    }

    const size_t WSZ = (size_t)DIMM * DIMM;
    dim3 gPrep(32, 32);
    prep_w<<<gPrep, 256>>>(wq, whi + 0 * WSZ, wlo + 0 * WSZ);
    prep_w<<<gPrep, 256>>>(wk, whi + 1 * WSZ, wlo + 1 * WSZ);
    prep_w<<<gPrep, 256>>>(wv, whi + 2 * WSZ, wlo + 2 * WSZ);
    prep_w<<<gPrep, 256>>>(wo, whi + 3 * WSZ, wlo + 3 * WSZ);

    split_f32<<<BS * DIMM / 4 / 256, 256>>>((const float4*)x, xhi, xlo);

    gemm_qkv<<<dim3(DIMM / 128, BS / 128, 3), 256, GEMM_SMEM>>>(
        xhi, xlo, whi, wlo, gq, gk, gv);

    rope_kernel<<<BS, 256>>>(gq, gk, Hm, Bm, fc, fs);

    split_f32<<<BS * DIMM / 4 / 256, 256>>>((const float4*)gq, qhi, qlo);
    split_f32<<<BS * DIMM / 4 / 256, 256>>>((const float4*)gk, khi, klo);
    split_f32<<<BS * DIMM / 4 / 256, 256>>>((const float4*)gv, vhi, vlo);

    flash_mma<<<dim3(SS / 128, BB * NH), 256, FLASH_SMEM>>>(
        qhi, qlo, khi, klo, vhi, vlo, masks, aohi, aolo);

    gemm_mma<<<dim3(DIMM / 128, BS / 128), 256, GEMM_SMEM>>>(
        aohi, aolo, whi + 3 * WSZ, wlo + 3 * WSZ, out, BS, DIMM, DIMM);
}

// round 7
// speedup vs baseline: 3.2981x; 1.0328x over previous
#include <cuda_runtime.h>
#include <cuda_bf16.h>

// Problem constants
#define BB   2
#define SS   1024
#define DIMM 1024
#define NH   16
#define HD   64
#define BS   (BB * SS)
#define NEG_INF_F (-1000000000.0f)

// ---------------------------------------------------------------------------
// Scratch (static device globals; no allocation anywhere)
// ---------------------------------------------------------------------------
__device__ float g_q [BS * DIMM];
__device__ float g_k [BS * DIMM];
__device__ __nv_bfloat16 g_xhi [BS * DIMM];
__device__ __nv_bfloat16 g_xlo [BS * DIMM];
__device__ __nv_bfloat16 g_aohi[BS * DIMM];
__device__ __nv_bfloat16 g_aolo[BS * DIMM];
__device__ __nv_bfloat16 g_whi [4 * DIMM * DIMM];  // transposed [n][k]
__device__ __nv_bfloat16 g_wlo [4 * DIMM * DIMM];
__device__ __nv_bfloat16 g_qhi [BS * DIMM];
__device__ __nv_bfloat16 g_qlo [BS * DIMM];
__device__ __nv_bfloat16 g_khi [BS * DIMM];
__device__ __nv_bfloat16 g_klo [BS * DIMM];
__device__ __nv_bfloat16 g_vhi [BS * DIMM];
__device__ __nv_bfloat16 g_vlo [BS * DIMM];

// ---------------------------------------------------------------------------
// PTX helpers (baseline ISA only)
// ---------------------------------------------------------------------------
__device__ __forceinline__ unsigned smem_u32(const void* p) {
    unsigned a;
    asm("{ .reg .u64 t; cvta.to.shared.u64 t, %1; cvt.u32.u64 %0, t; }"
        : "=r"(a) : "l"(p));
    return a;
}

__device__ __forceinline__ void cp_async16(unsigned saddr, const void* gaddr) {
    asm volatile("cp.async.cg.shared.global [%0], [%1], 16;"
                 :: "r"(saddr), "l"(gaddr));
}
#define CP_COMMIT() asm volatile("cp.async.commit_group;")
template <int N>
__device__ __forceinline__ void cp_wait() {
    asm volatile("cp.async.wait_group %0;" :: "n"(N));
}

__device__ __forceinline__ void ldm_x4(unsigned addr, unsigned* r) {
    asm volatile("ldmatrix.sync.aligned.m8n8.x4.shared.b16 {%0,%1,%2,%3}, [%4];"
                 : "=r"(r[0]), "=r"(r[1]), "=r"(r[2]), "=r"(r[3]) : "r"(addr));
}

__device__ __forceinline__ void ldm_x4_t(unsigned addr, unsigned* r) {
    asm volatile("ldmatrix.sync.aligned.m8n8.x4.trans.shared.b16 {%0,%1,%2,%3}, [%4];"
                 : "=r"(r[0]), "=r"(r[1]), "=r"(r[2]), "=r"(r[3]) : "r"(addr));
}

__device__ __forceinline__ void mma_bf16(float* c, const unsigned* a,
                                         const unsigned* b) {
    asm volatile(
        "mma.sync.aligned.m16n8k16.row.col.f32.bf16.bf16.f32 "
        "{%0,%1,%2,%3}, {%4,%5,%6,%7}, {%8,%9}, {%0,%1,%2,%3};"
        : "+f"(c[0]), "+f"(c[1]), "+f"(c[2]), "+f"(c[3])
        : "r"(a[0]), "r"(a[1]), "r"(a[2]), "r"(a[3]), "r"(b[0]), "r"(b[1]));
}

__device__ __forceinline__ unsigned pk2(float x, float y) {
    __nv_bfloat162 t = __floats2bfloat162_rn(x, y);
    return *(unsigned*)&t;
}

// split a float pair into hi pair + lo pair (packed bf16x2 words)
__device__ __forceinline__ void split2(float x, float y, unsigned& hw, unsigned& lw) {
    hw = pk2(x, y);
    __nv_bfloat162* hp = (__nv_bfloat162*)&hw;
    lw = pk2(x - __bfloat162float(hp->x), y - __bfloat162float(hp->y));
}

// ---------------------------------------------------------------------------
// Weight prep (all 4 weights in one launch): fp32 w[k][n] -> bf16 hi/lo [n][k]
// grid (32, 32, 4)
// ---------------------------------------------------------------------------
__global__ __launch_bounds__(256) void prep_w4(const float* __restrict__ w0,
                                               const float* __restrict__ w1,
                                               const float* __restrict__ w2,
                                               const float* __restrict__ w3,
                                               __nv_bfloat16* __restrict__ hi,
                                               __nv_bfloat16* __restrict__ lo)
{
    __shared__ float t[32][33];
    const int z = blockIdx.z;
    const float* w = (z == 0) ? w0 : (z == 1) ? w1 : (z == 2) ? w2 : w3;
    hi += (size_t)z * DIMM * DIMM;
    lo += (size_t)z * DIMM * DIMM;

    const int tx = threadIdx.x & 31, ty = threadIdx.x >> 5;
    const int n0 = blockIdx.x * 32, k0 = blockIdx.y * 32;
#pragma unroll
    for (int i = 0; i < 4; i++)
        t[ty + 8 * i][tx] = w[(size_t)(k0 + ty + 8 * i) * DIMM + n0 + tx];
    __syncthreads();
#pragma unroll
    for (int i = 0; i < 4; i++) {
        float v = t[tx][ty + 8 * i];
        __nv_bfloat16 h = __float2bfloat16_rn(v);
        float r = v - __bfloat162float(h);
        size_t o = (size_t)(n0 + ty + 8 * i) * DIMM + k0 + tx;
        hi[o] = h;
        lo[o] = __float2bfloat16_rn(r);
    }
}

// ---------------------------------------------------------------------------
// Activation split: fp32 -> bf16 hi/lo (only used for x now)
// ---------------------------------------------------------------------------
__global__ __launch_bounds__(256) void split_f32(const float4* __restrict__ in,
                                                 __nv_bfloat16* __restrict__ hi,
                                                 __nv_bfloat16* __restrict__ lo)
{
    const int i = blockIdx.x * 256 + threadIdx.x;
    float4 v = in[i];
    unsigned hw0, lw0, hw1, lw1;
    split2(v.x, v.y, hw0, lw0);
    split2(v.z, v.w, hw1, lw1);
    ((uint2*)hi)[i] = make_uint2(hw0, hw1);
    ((uint2*)lo)[i] = make_uint2(lw0, lw1);
}

// ---------------------------------------------------------------------------
// MMA GEMM core (128x128 tile, BK=32, 3-stage).
// ---------------------------------------------------------------------------
#define BK        32
#define ROW_ELEMS 40
#define ROW_BYTES (ROW_ELEMS * 2)
#define TILE_B    (128 * ROW_BYTES)
#define STAGE_B   (4 * TILE_B)
#define NSTAGE    3
#define GEMM_SMEM (NSTAGE * STAGE_B)

// MODE 0: write fp32 C. MODE 1: write split bf16 (Chi/Clo).
template <int MODE>
__device__ __forceinline__ void gemm_body(
    const __nv_bfloat16* __restrict__ Ahi, const __nv_bfloat16* __restrict__ Alo,
    const __nv_bfloat16* __restrict__ Bhi, const __nv_bfloat16* __restrict__ Blo,
    float* __restrict__ C, __nv_bfloat16* __restrict__ Chi,
    __nv_bfloat16* __restrict__ Clo,
    int M, int N, int K, int row0, int col0)
{
    extern __shared__ char smem[];
    const unsigned sb = smem_u32(smem);

    const int tid  = threadIdx.x;
    const int lane = tid & 31;
    const int wid  = tid >> 5;
    const int wm   = wid & 1;
    const int wn   = wid >> 1;

    const int t0r = tid >> 2, t0s = tid & 3;
    const int t1r = t0r + 64;
    const size_t gA0 = (size_t)(row0 + t0r) * K + t0s * 8;
    const size_t gA1 = (size_t)(row0 + t1r) * K + t0s * 8;
    const size_t gB0 = (size_t)(col0 + t0r) * K + t0s * 8;
    const size_t gB1 = (size_t)(col0 + t1r) * K + t0s * 8;
    const unsigned s0 = t0r * ROW_BYTES + t0s * 16;
    const unsigned s1 = t1r * ROW_BYTES + t0s * 16;

#define LOAD_CHUNK(c, stg) do {                                              \
    const int kk = (c) * BK;                                                 \
    unsigned base = sb + (stg) * STAGE_B;                                    \
    cp_async16(base + 0 * TILE_B + s0, Ahi + gA0 + kk);                      \
    cp_async16(base + 0 * TILE_B + s1, Ahi + gA1 + kk);                      \
    cp_async16(base + 1 * TILE_B + s0, Alo + gA0 + kk);                      \
    cp_async16(base + 1 * TILE_B + s1, Alo + gA1 + kk);                      \
    cp_async16(base + 2 * TILE_B + s0, Bhi + gB0 + kk);                      \
    cp_async16(base + 2 * TILE_B + s1, Bhi + gB1 + kk);                      \
    cp_async16(base + 3 * TILE_B + s0, Blo + gB0 + kk);                      \
    cp_async16(base + 3 * TILE_B + s1, Blo + gB1 + kk);                      \
} while (0)

    float acc[4][4][4];
#pragma unroll
    for (int i = 0; i < 4; i++)
#pragma unroll
        for (int j = 0; j < 4; j++)
#pragma unroll
            for (int q = 0; q < 4; q++) acc[i][j][q] = 0.0f;

    const int l7 = lane & 7, m4 = lane >> 3;
    const unsigned aoff = (wm * 64 + (m4 & 1) * 8 + l7) * ROW_BYTES + (m4 >> 1) * 16;
    const unsigned boff = (wn * 32 + ((m4 & 2) ? 8 : 0) + l7) * ROW_BYTES + (m4 & 1) * 16;

    const int NCH = K / BK;

    LOAD_CHUNK(0, 0); CP_COMMIT();
    LOAD_CHUNK(1, 1); CP_COMMIT();

    for (int c = 0; c < NCH; c++) {
        cp_wait<1>();
        __syncthreads();

        if (c + 2 < NCH) LOAD_CHUNK(c + 2, (c + 2) % NSTAGE);
        CP_COMMIT();

        const unsigned stg = sb + (c % NSTAGE) * STAGE_B;
#pragma unroll
        for (int ks = 0; ks < 2; ks++) {
            const unsigned kb = ks * 32;
            unsigned ah[4][4], al[4][4], bh[2][4], bl[2][4];
#pragma unroll
            for (int mi = 0; mi < 4; mi++) {
                unsigned ad = stg + aoff + mi * (16 * ROW_BYTES) + kb;
                ldm_x4(ad + 0 * TILE_B, ah[mi]);
                ldm_x4(ad + 1 * TILE_B, al[mi]);
            }
#pragma unroll
            for (int ng = 0; ng < 2; ng++) {
                unsigned bd = stg + boff + ng * (16 * ROW_BYTES) + kb;
                ldm_x4(bd + 2 * TILE_B, bh[ng]);
                ldm_x4(bd + 3 * TILE_B, bl[ng]);
            }
#pragma unroll
            for (int mi = 0; mi < 4; mi++)
#pragma unroll
                for (int ni = 0; ni < 4; ni++) {
                    const int ng = ni >> 1, half = (ni & 1) * 2;
                    unsigned bhr[2] = { bh[ng][half], bh[ng][half + 1] };
                    unsigned blr[2] = { bl[ng][half], bl[ng][half + 1] };
                    mma_bf16(acc[mi][ni], ah[mi], bhr);
                    mma_bf16(acc[mi][ni], ah[mi], blr);
                    mma_bf16(acc[mi][ni], al[mi], bhr);
                }
        }
        __syncthreads();
    }

    const int erow = row0 + wm * 64 + (lane >> 2);
    const int ecol = col0 + wn * 32 + (lane & 3) * 2;
#pragma unroll
    for (int mi = 0; mi < 4; mi++)
#pragma unroll
        for (int ni = 0; ni < 4; ni++) {
            const size_t o0 = (size_t)(erow + mi * 16) * N + ecol + ni * 8;
            const size_t o1 = o0 + (size_t)8 * N;
            if (MODE == 0) {
                C[o0] = acc[mi][ni][0]; C[o0 + 1] = acc[mi][ni][1];
                C[o1] = acc[mi][ni][2]; C[o1 + 1] = acc[mi][ni][3];
            } else {
                unsigned h0, l0w, h1, l1w;
                split2(acc[mi][ni][0], acc[mi][ni][1], h0, l0w);
                split2(acc[mi][ni][2], acc[mi][ni][3], h1, l1w);
                *(unsigned*)(Chi + o0) = h0;
                *(unsigned*)(Clo + o0) = l0w;
                *(unsigned*)(Chi + o1) = h1;
                *(unsigned*)(Clo + o1) = l1w;
            }
        }
#undef LOAD_CHUNK
}

__global__ __launch_bounds__(256) void gemm_mma(
    const __nv_bfloat16* __restrict__ Ahi, const __nv_bfloat16* __restrict__ Alo,
    const __nv_bfloat16* __restrict__ Bhi, const __nv_bfloat16* __restrict__ Blo,
    float* __restrict__ C, int M, int N, int K)
{
    gemm_body<0>(Ahi, Alo, Bhi, Blo, C, nullptr, nullptr, M, N, K,
                 blockIdx.y * 128, blockIdx.x * 128);
}

// Fused QKV: z=0 -> q fp32, z=1 -> k fp32, z=2 -> v split bf16.
__global__ __launch_bounds__(256) void gemm_qkv(
    const __nv_bfloat16* __restrict__ Ahi, const __nv_bfloat16* __restrict__ Alo,
    const __nv_bfloat16* __restrict__ Whi, const __nv_bfloat16* __restrict__ Wlo,
    float* __restrict__ Cq, float* __restrict__ Ck,
    __nv_bfloat16* __restrict__ Vhi, __nv_bfloat16* __restrict__ Vlo)
{
    const size_t WSZ = (size_t)DIMM * DIMM;
    const int z = blockIdx.z;
    const __nv_bfloat16* Bhi = Whi + (size_t)z * WSZ;
    const __nv_bfloat16* Blo = Wlo + (size_t)z * WSZ;
    if (z == 2) {
        gemm_body<1>(Ahi, Alo, Bhi, Blo, nullptr, Vhi, Vlo, BS, DIMM, DIMM,
                     blockIdx.y * 128, blockIdx.x * 128);
    } else {
        float* C = (z == 0) ? Cq : Ck;
        gemm_body<0>(Ahi, Alo, Bhi, Blo, C, nullptr, nullptr, BS, DIMM, DIMM,
                     blockIdx.y * 128, blockIdx.x * 128);
    }
}

// ---------------------------------------------------------------------------
// Flash attention (unchanged from R6)
// ---------------------------------------------------------------------------
#define FROWB  144
#define FTILE  (128 * FROWB)
#define FSTAGE (4 * FTILE)
#define FLASH_SMEM (2 * FTILE + 2 * FSTAGE)

__global__ __launch_bounds__(256, 1) void flash_mma(
    const __nv_bfloat16* __restrict__ qhi, const __nv_bfloat16* __restrict__ qlo,
    const __nv_bfloat16* __restrict__ khi, const __nv_bfloat16* __restrict__ klo,
    const __nv_bfloat16* __restrict__ vhi, const __nv_bfloat16* __restrict__ vlo,
    const int* __restrict__ masks,
    __nv_bfloat16* __restrict__ aohi, __nv_bfloat16* __restrict__ aolo)
{
    extern __shared__ char smem[];
    const unsigned sb = smem_u32(smem);
    const int tid = threadIdx.x, lane = tid & 31, wid = tid >> 5;
    const int bh = blockIdx.y, b = bh >> 4, h = bh & 15;
    const int q0 = blockIdx.x * 128;
    const int wq0 = wid * 16;

    const unsigned sQh = sb, sQl = sb + FTILE;

#pragma unroll
    for (int t = 0; t < 4; t++) {
        int seg = tid + t * 256, row = seg >> 3, s = seg & 7;
        size_t g = (size_t)(b * SS + q0 + row) * DIMM + h * HD + s * 8;
        unsigned sa = row * FROWB + s * 16;
        cp_async16(sQh + sa, qhi + g);
        cp_async16(sQl + sa, qlo + g);
    }

#define KV_LOAD(kt, stg) do {                                                \
    unsigned base = sb + 2 * FTILE + (stg) * FSTAGE;                         \
    _Pragma("unroll")                                                        \
    for (int t = 0; t < 4; t++) {                                            \
        int seg = tid + t * 256, row = seg >> 3, s = seg & 7;                \
        size_t g = (size_t)(b * SS + (kt) * 128 + row) * DIMM + h * HD + s * 8; \
        unsigned sa = row * FROWB + s * 16;                                  \
        cp_async16(base + sa,             khi + g);                          \
        cp_async16(base + FTILE + sa,     klo + g);                          \
        cp_async16(base + 2 * FTILE + sa, vhi + g);                          \
        cp_async16(base + 3 * FTILE + sa, vlo + g);                          \
    }                                                                        \
} while (0)

    KV_LOAD(0, 0); CP_COMMIT();
    KV_LOAD(1, 1); CP_COMMIT();

    float m0 = -1e30f, m1 = -1e30f, l0 = 0.0f, l1 = 0.0f;
    float acc_o[8][4];
#pragma unroll
    for (int j = 0; j < 8; j++)
#pragma unroll
        for (int q = 0; q < 4; q++) acc_o[j][q] = 0.0f;

    const int l7 = lane & 7, m4 = lane >> 3;
    const unsigned qoff = (wq0 + (m4 & 1) * 8 + l7) * FROWB + (m4 >> 1) * 16;
    const unsigned koff = (((m4 & 2) ? 8 : 0) + l7) * FROWB + (m4 & 1) * 16;
    const unsigned voff = (lane & 15) * FROWB + (lane >> 4) * 16;

    const int gr0 = q0 + wq0 + (lane >> 2);
    const int* mrow0 = masks + (size_t)b * SS * SS + (size_t)gr0 * SS;
    const int* mrow1 = mrow0 + 8 * SS;

    for (int kt = 0; kt < 8; kt++) {
        if (kt == 7) cp_wait<0>(); else cp_wait<1>();
        __syncthreads();
        const unsigned kbase = sb + 2 * FTILE + (kt & 1) * FSTAGE;

        float s[16][4];
#pragma unroll
        for (int ni = 0; ni < 16; ni++)
#pragma unroll
            for (int q = 0; q < 4; q++) s[ni][q] = 0.0f;

#pragma unroll
        for (int ks = 0; ks < 4; ks++) {
            unsigned ah[4], al[4];
            ldm_x4(sQh + qoff + ks * 32, ah);
            ldm_x4(sQl + qoff + ks * 32, al);
#pragma unroll
            for (int g = 0; g < 8; g++) {
                unsigned bh4[4], bl4[4];
                unsigned ba = kbase + koff + g * (16 * FROWB) + ks * 32;
                ldm_x4(ba, bh4);
                ldm_x4(ba + FTILE, bl4);
                unsigned bh0[2] = { bh4[0], bh4[1] }, bh1[2] = { bh4[2], bh4[3] };
                unsigned bl0[2] = { bl4[0], bl4[1] }, bl1[2] = { bl4[2], bl4[3] };
                mma_bf16(s[2 * g],     ah, bh0); mma_bf16(s[2 * g],     ah, bl0); mma_bf16(s[2 * g],     al, bh0);
                mma_bf16(s[2 * g + 1], ah, bh1); mma_bf16(s[2 * g + 1], ah, bl1); mma_bf16(s[2 * g + 1], al, bh1);
            }
        }

        const int kc0 = kt * 128 + (lane & 3) * 2;
#pragma unroll
        for (int ni = 0; ni < 16; ni++) {
            int2 mk0 = *(const int2*)(mrow0 + kc0 + ni * 8);
            int2 mk1 = *(const int2*)(mrow1 + kc0 + ni * 8);
            s[ni][0] = mk0.x ? s[ni][0] * 0.125f : NEG_INF_F;
            s[ni][1] = mk0.y ? s[ni][1] * 0.125f : NEG_INF_F;
            s[ni][2] = mk1.x ? s[ni][2] * 0.125f : NEG_INF_F;
            s[ni][3] = mk1.y ? s[ni][3] * 0.125f : NEG_INF_F;
        }

        float mx0 = -1e30f, mx1 = -1e30f;
#pragma unroll
        for (int ni = 0; ni < 16; ni++) {
            mx0 = fmaxf(mx0, fmaxf(s[ni][0], s[ni][1]));
            mx1 = fmaxf(mx1, fmaxf(s[ni][2], s[ni][3]));
        }
        mx0 = fmaxf(mx0, __shfl_xor_sync(0xffffffffu, mx0, 1));
        mx0 = fmaxf(mx0, __shfl_xor_sync(0xffffffffu, mx0, 2));
        mx1 = fmaxf(mx1, __shfl_xor_sync(0xffffffffu, mx1, 1));
        mx1 = fmaxf(mx1, __shfl_xor_sync(0xffffffffu, mx1, 2));

        float mn0 = fmaxf(m0, mx0), mn1 = fmaxf(m1, mx1);
        float al0 = __expf(m0 - mn0), al1 = __expf(m1 - mn1);
        m0 = mn0; m1 = mn1;

        float sum0 = 0.0f, sum1 = 0.0f;
#pragma unroll
        for (int ni = 0; ni < 16; ni++) {
            s[ni][0] = __expf(s[ni][0] - mn0);
            s[ni][1] = __expf(s[ni][1] - mn0);
            s[ni][2] = __expf(s[ni][2] - mn1);
            s[ni][3] = __expf(s[ni][3] - mn1);
            sum0 += s[ni][0] + s[ni][1];
            sum1 += s[ni][2] + s[ni][3];
        }
        sum0 += __shfl_xor_sync(0xffffffffu, sum0, 1);
        sum0 += __shfl_xor_sync(0xffffffffu, sum0, 2);
        sum1 += __shfl_xor_sync(0xffffffffu, sum1, 1);
        sum1 += __shfl_xor_sync(0xffffffffu, sum1, 2);
        l0 = l0 * al0 + sum0;
        l1 = l1 * al1 + sum1;

#pragma unroll
        for (int j = 0; j < 8; j++) {
            acc_o[j][0] *= al0; acc_o[j][1] *= al0;
            acc_o[j][2] *= al1; acc_o[j][3] *= al1;
        }

#pragma unroll
        for (int kc = 0; kc < 8; kc++) {
            unsigned aH[4], aL[4];
            split2(s[2 * kc][0],     s[2 * kc][1],     aH[0], aL[0]);
            split2(s[2 * kc][2],     s[2 * kc][3],     aH[1], aL[1]);
            split2(s[2 * kc + 1][0], s[2 * kc + 1][1], aH[2], aL[2]);
            split2(s[2 * kc + 1][2], s[2 * kc + 1][3], aH[3], aL[3]);
#pragma unroll
            for (int dg = 0; dg < 4; dg++) {
                unsigned bh4[4], bl4[4];
                unsigned va = kbase + 2 * FTILE + voff + kc * (16 * FROWB) + dg * 32;
                ldm_x4_t(va, bh4);
                ldm_x4_t(va + FTILE, bl4);
                unsigned b0h[2] = { bh4[0], bh4[1] }, b1h[2] = { bh4[2], bh4[3] };
                unsigned b0l[2] = { bl4[0], bl4[1] }, b1l[2] = { bl4[2], bl4[3] };
                mma_bf16(acc_o[2 * dg],     aH, b0h);
                mma_bf16(acc_o[2 * dg],     aH, b0l);
                mma_bf16(acc_o[2 * dg],     aL, b0h);
                mma_bf16(acc_o[2 * dg + 1], aH, b1h);
                mma_bf16(acc_o[2 * dg + 1], aH, b1l);
                mma_bf16(acc_o[2 * dg + 1], aL, b1h);
            }
        }

        __syncthreads();
        if (kt + 2 < 8) { KV_LOAD(kt + 2, kt & 1); CP_COMMIT(); }
    }

    const float inv0 = 1.0f / l0, inv1 = 1.0f / l1;
    const size_t o0 = (size_t)(b * SS + gr0) * DIMM + h * HD + (lane & 3) * 2;
    const size_t o1 = o0 + (size_t)8 * DIMM;
#pragma unroll
    for (int j = 0; j < 8; j++) {
        unsigned h0, w0, h1, w1;
        split2(acc_o[j][0] * inv0, acc_o[j][1] * inv0, h0, w0);
        split2(acc_o[j][2] * inv1, acc_o[j][3] * inv1, h1, w1);
        *(unsigned*)(aohi + o0 + j * 8) = h0;
        *(unsigned*)(aolo + o0 + j * 8) = w0;
        *(unsigned*)(aohi + o1 + j * 8) = h1;
        *(unsigned*)(aolo + o1 + j * 8) = w1;
    }
#undef KV_LOAD
}

// ---------------------------------------------------------------------------
// RoPE: reads fp32 q/k, applies rotations, writes split bf16 hi/lo directly.
// ---------------------------------------------------------------------------
#define ROT(xx, yy, c, s) { float _t = (xx)*(c) - (yy)*(s); (yy) = (xx)*(s) + (yy)*(c); (xx) = _t; }

__global__ __launch_bounds__(256) void rope_split(const float* __restrict__ q,
                                                  const float* __restrict__ k,
                                                  const int* __restrict__ Hm,
                                                  const int* __restrict__ Bm,
                                                  const float* __restrict__ fc,
                                                  const float* __restrict__ fs,
                                                  __nv_bfloat16* __restrict__ qhi,
                                                  __nv_bfloat16* __restrict__ qlo,
                                                  __nv_bfloat16* __restrict__ khi,
                                                  __nv_bfloat16* __restrict__ klo)
{
    const int tok = blockIdx.x;
    const int tid = threadIdx.x;
    const int h = tid >> 4;
    const int m = tid & 15;
    const int base = tok * DIMM + h * HD;

    float2 qab = *(const float2*)&q[base + 2 * m];
    float2 qcd = *(const float2*)&q[base + 2 * m + 32];
    float2 kab = *(const float2*)&k[base + 2 * m];
    float2 kcd = *(const float2*)&k[base + 2 * m + 32];

    const float cH0 = fc[32 + m],      sH0 = fs[32 + m];
    const float cH1 = fc[32 + m + 16], sH1 = fs[32 + m + 16];
    const float cB0a = fc[32 + 2 * m],     sB0a = fs[32 + 2 * m];
    const float cB0b = fc[32 + 2 * m + 1], sB0b = fs[32 + 2 * m + 1];
    const float cB1a = fc[64 + 2 * m],     sB1a = fs[64 + 2 * m];
    const float cB1b = fc[64 + 2 * m + 1], sB1b = fs[64 + 2 * m + 1];

#pragma unroll
    for (int i = 0; i < 6; i++) {
        if (Hm[i * BS + tok]) {
            ROT(qab.x, qab.y, cH0, sH0); ROT(qcd.x, qcd.y, cH1, sH1);
            ROT(kab.x, kab.y, cH0, sH0); ROT(kcd.x, kcd.y, cH1, sH1);
        }
        if (Bm[(i * 2 + 0) * BS + tok]) {
            ROT(qab.x, qcd.x, cB0a, sB0a); ROT(qab.y, qcd.y, cB0b, sB0b);
            ROT(kab.x, kcd.x, cB0a, sB0a); ROT(kab.y, kcd.y, cB0b, sB0b);
        }
        if (Bm[(i * 2 + 1) * BS + tok]) {
            ROT(qab.x, qcd.x, cB1a, sB1a); ROT(qab.y, qcd.y, cB1b, sB1b);
            ROT(kab.x, kcd.x, cB1a, sB1a); ROT(kab.y, kcd.y, cB1b, sB1b);
        }
    }

    unsigned hw, lw;
    split2(qab.x, qab.y, hw, lw);
    *(unsigned*)(qhi + base + 2 * m) = hw;  *(unsigned*)(qlo + base + 2 * m) = lw;
    split2(qcd.x, qcd.y, hw, lw);
    *(unsigned*)(qhi + base + 2 * m + 32) = hw;  *(unsigned*)(qlo + base + 2 * m + 32) = lw;
    split2(kab.x, kab.y, hw, lw);
    *(unsigned*)(khi + base + 2 * m) = hw;  *(unsigned*)(klo + base + 2 * m) = lw;
    split2(kcd.x, kcd.y, hw, lw);
    *(unsigned*)(khi + base + 2 * m + 32) = hw;  *(unsigned*)(klo + base + 2 * m + 32) = lw;
}

// ---------------------------------------------------------------------------
extern "C" void kernel_launch(void* const* d_in, const int* in_sizes, int n_in,
                              void* d_out, int out_size)
{
    const float* x     = (const float*)d_in[0];
    const int*   masks = (const int*)d_in[1];
    const int*   Hm    = (const int*)d_in[2];
    const int*   Bm    = (const int*)d_in[3];
    const float* fc    = (const float*)d_in[4];
    const float* fs    = (const float*)d_in[5];
    const float* wq    = (const float*)d_in[6];
    const float* wk    = (const float*)d_in[7];
    const float* wv    = (const float*)d_in[8];
    const float* wo    = (const float*)d_in[9];
    float* out = (float*)d_out;

    float *gq, *gk;
    __nv_bfloat16 *xhi, *xlo, *aohi, *aolo, *whi, *wlo;
    __nv_bfloat16 *qhi, *qlo, *khi, *klo, *vhi, *vlo;
    cudaGetSymbolAddress((void**)&gq,   g_q);
    cudaGetSymbolAddress((void**)&gk,   g_k);
    cudaGetSymbolAddress((void**)&xhi,  g_xhi);
    cudaGetSymbolAddress((void**)&xlo,  g_xlo);
    cudaGetSymbolAddress((void**)&aohi, g_aohi);
    cudaGetSymbolAddress((void**)&aolo, g_aolo);
    cudaGetSymbolAddress((void**)&whi,  g_whi);
    cudaGetSymbolAddress((void**)&wlo,  g_wlo);
    cudaGetSymbolAddress((void**)&qhi,  g_qhi);
    cudaGetSymbolAddress((void**)&qlo,  g_qlo);
    cudaGetSymbolAddress((void**)&khi,  g_khi);
    cudaGetSymbolAddress((void**)&klo,  g_klo);
    cudaGetSymbolAddress((void**)&vhi,  g_vhi);
    cudaGetSymbolAddress((void**)&vlo,  g_vlo);

    static bool attr_done = false;
    if (!attr_done) {
        cudaFuncSetAttribute(gemm_mma,  cudaFuncAttributeMaxDynamicSharedMemorySize, GEMM_SMEM);
        cudaFuncSetAttribute(gemm_qkv,  cudaFuncAttributeMaxDynamicSharedMemorySize, GEMM_SMEM);
        cudaFuncSetAttribute(flash_mma, cudaFuncAttributeMaxDynamicSharedMemorySize, FLASH_SMEM);
        attr_done = true;
    }

    prep_w4<<<dim3(32, 32, 4), 256>>>(wq, wk, wv, wo, whi, wlo);

    split_f32<<<BS * DIMM / 4 / 256, 256>>>((const float4*)x, xhi, xlo);

    gemm_qkv<<<dim3(DIMM / 128, BS / 128, 3), 256, GEMM_SMEM>>>(
        xhi, xlo, whi, wlo, gq, gk, vhi, vlo);

    rope_split<<<BS, 256>>>(gq, gk, Hm, Bm, fc, fs, qhi, qlo, khi, klo);

    flash_mma<<<dim3(SS / 128, BB * NH), 256, FLASH_SMEM>>>(
        qhi, qlo, khi, klo, vhi, vlo, masks, aohi, aolo);

    gemm_mma<<<dim3(DIMM / 128, BS / 128), 256, GEMM_SMEM>>>(
        aohi, aolo, whi + 3 * (size_t)DIMM * DIMM, wlo + 3 * (size_t)DIMM * DIMM,
        out, BS, DIMM, DIMM);
}

// round 8
// speedup vs baseline: 3.3689x; 1.0215x over previous
#include <cuda_runtime.h>
#include <cuda_bf16.h>

// Problem constants
#define BB   2
#define SS   1024
#define DIMM 1024
#define NH   16
#define HD   64
#define BS   (BB * SS)
#define NEG_INF_F (-1000000000.0f)

// ---------------------------------------------------------------------------
// Scratch (static device globals; no allocation anywhere)
// ---------------------------------------------------------------------------
__device__ float g_q [BS * DIMM];
__device__ float g_k [BS * DIMM];
__device__ __nv_bfloat16 g_xhi [BS * DIMM];
__device__ __nv_bfloat16 g_xlo [BS * DIMM];
__device__ __nv_bfloat16 g_aohi[BS * DIMM];
__device__ __nv_bfloat16 g_aolo[BS * DIMM];
__device__ __nv_bfloat16 g_whi [4 * DIMM * DIMM];  // transposed [n][k]
__device__ __nv_bfloat16 g_wlo [4 * DIMM * DIMM];
__device__ __nv_bfloat16 g_qhi [BS * DIMM];
__device__ __nv_bfloat16 g_qlo [BS * DIMM];
__device__ __nv_bfloat16 g_khi [BS * DIMM];
__device__ __nv_bfloat16 g_klo [BS * DIMM];
__device__ __nv_bfloat16 g_vhi [BS * DIMM];
__device__ __nv_bfloat16 g_vlo [BS * DIMM];

// ---------------------------------------------------------------------------
// PTX helpers (baseline ISA only)
// ---------------------------------------------------------------------------
__device__ __forceinline__ unsigned smem_u32(const void* p) {
    unsigned a;
    asm("{ .reg .u64 t; cvta.to.shared.u64 t, %1; cvt.u32.u64 %0, t; }"
        : "=r"(a) : "l"(p));
    return a;
}

__device__ __forceinline__ void cp_async16(unsigned saddr, const void* gaddr) {
    asm volatile("cp.async.cg.shared.global [%0], [%1], 16;"
                 :: "r"(saddr), "l"(gaddr));
}
#define CP_COMMIT() asm volatile("cp.async.commit_group;")
template <int N>
__device__ __forceinline__ void cp_wait() {
    asm volatile("cp.async.wait_group %0;" :: "n"(N));
}

__device__ __forceinline__ void ldm_x4(unsigned addr, unsigned* r) {
    asm volatile("ldmatrix.sync.aligned.m8n8.x4.shared.b16 {%0,%1,%2,%3}, [%4];"
                 : "=r"(r[0]), "=r"(r[1]), "=r"(r[2]), "=r"(r[3]) : "r"(addr));
}

__device__ __forceinline__ void ldm_x4_t(unsigned addr, unsigned* r) {
    asm volatile("ldmatrix.sync.aligned.m8n8.x4.trans.shared.b16 {%0,%1,%2,%3}, [%4];"
                 : "=r"(r[0]), "=r"(r[1]), "=r"(r[2]), "=r"(r[3]) : "r"(addr));
}

__device__ __forceinline__ void mma_bf16(float* c, const unsigned* a,
                                         const unsigned* b) {
    asm volatile(
        "mma.sync.aligned.m16n8k16.row.col.f32.bf16.bf16.f32 "
        "{%0,%1,%2,%3}, {%4,%5,%6,%7}, {%8,%9}, {%0,%1,%2,%3};"
        : "+f"(c[0]), "+f"(c[1]), "+f"(c[2]), "+f"(c[3])
        : "r"(a[0]), "r"(a[1]), "r"(a[2]), "r"(a[3]), "r"(b[0]), "r"(b[1]));
}

__device__ __forceinline__ unsigned pk2(float x, float y) {
    __nv_bfloat162 t = __floats2bfloat162_rn(x, y);
    return *(unsigned*)&t;
}

__device__ __forceinline__ void split2(float x, float y, unsigned& hw, unsigned& lw) {
    hw = pk2(x, y);
    __nv_bfloat162* hp = (__nv_bfloat162*)&hw;
    lw = pk2(x - __bfloat162float(hp->x), y - __bfloat162float(hp->y));
}

// ---------------------------------------------------------------------------
// Weight prep (all 4 weights, one launch)
// ---------------------------------------------------------------------------
__global__ __launch_bounds__(256) void prep_w4(const float* __restrict__ w0,
                                               const float* __restrict__ w1,
                                               const float* __restrict__ w2,
                                               const float* __restrict__ w3,
                                               __nv_bfloat16* __restrict__ hi,
                                               __nv_bfloat16* __restrict__ lo)
{
    __shared__ float t[32][33];
    const int z = blockIdx.z;
    const float* w = (z == 0) ? w0 : (z == 1) ? w1 : (z == 2) ? w2 : w3;
    hi += (size_t)z * DIMM * DIMM;
    lo += (size_t)z * DIMM * DIMM;

    const int tx = threadIdx.x & 31, ty = threadIdx.x >> 5;
    const int n0 = blockIdx.x * 32, k0 = blockIdx.y * 32;
#pragma unroll
    for (int i = 0; i < 4; i++)
        t[ty + 8 * i][tx] = w[(size_t)(k0 + ty + 8 * i) * DIMM + n0 + tx];
    __syncthreads();
#pragma unroll
    for (int i = 0; i < 4; i++) {
        float v = t[tx][ty + 8 * i];
        __nv_bfloat16 h = __float2bfloat16_rn(v);
        float r = v - __bfloat162float(h);
        size_t o = (size_t)(n0 + ty + 8 * i) * DIMM + k0 + tx;
        hi[o] = h;
        lo[o] = __float2bfloat16_rn(r);
    }
}

// ---------------------------------------------------------------------------
// Activation split: fp32 -> bf16 hi/lo (x only)
// ---------------------------------------------------------------------------
__global__ __launch_bounds__(256) void split_f32(const float4* __restrict__ in,
                                                 __nv_bfloat16* __restrict__ hi,
                                                 __nv_bfloat16* __restrict__ lo)
{
    const int i = blockIdx.x * 256 + threadIdx.x;
    float4 v = in[i];
    unsigned hw0, lw0, hw1, lw1;
    split2(v.x, v.y, hw0, lw0);
    split2(v.z, v.w, hw1, lw1);
    ((uint2*)hi)[i] = make_uint2(hw0, hw1);
    ((uint2*)lo)[i] = make_uint2(lw0, lw1);
}

// ---------------------------------------------------------------------------
// MMA GEMM core: 128x128 tile, BK=32, 3-stage, 512 threads (16 warps, 32x32
// warp tiles) for 4 warps/SMSP latency hiding on the 3-pass HMMA chains.
// ---------------------------------------------------------------------------
#define BK        32
#define ROW_ELEMS 40
#define ROW_BYTES (ROW_ELEMS * 2)
#define TILE_B    (128 * ROW_BYTES)
#define STAGE_B   (4 * TILE_B)
#define NSTAGE    3
#define GEMM_SMEM (NSTAGE * STAGE_B)
#define GT        512

// MODE 0: write fp32 C. MODE 1: write split bf16 (Chi/Clo).
template <int MODE>
__device__ __forceinline__ void gemm_body(
    const __nv_bfloat16* __restrict__ Ahi, const __nv_bfloat16* __restrict__ Alo,
    const __nv_bfloat16* __restrict__ Bhi, const __nv_bfloat16* __restrict__ Blo,
    float* __restrict__ C, __nv_bfloat16* __restrict__ Chi,
    __nv_bfloat16* __restrict__ Clo,
    int M, int N, int K, int row0, int col0)
{
    extern __shared__ char smem[];
    const unsigned sb = smem_u32(smem);

    const int tid  = threadIdx.x;
    const int lane = tid & 31;
    const int wid  = tid >> 5;
    const int wm   = wid & 3;        // 4 groups of 32 rows
    const int wn   = wid >> 2;       // 4 groups of 32 cols

    // loader: 512 segs per tile (128 rows x 4 of 16B), exactly 1 per thread
    const int t0r = tid >> 2, t0s = tid & 3;
    const size_t gA0 = (size_t)(row0 + t0r) * K + t0s * 8;
    const size_t gB0 = (size_t)(col0 + t0r) * K + t0s * 8;
    const unsigned s0 = t0r * ROW_BYTES + t0s * 16;

#define LOAD_CHUNK(c, stg) do {                                              \
    const int kk = (c) * BK;                                                 \
    unsigned base = sb + (stg) * STAGE_B;                                    \
    cp_async16(base + 0 * TILE_B + s0, Ahi + gA0 + kk);                      \
    cp_async16(base + 1 * TILE_B + s0, Alo + gA0 + kk);                      \
    cp_async16(base + 2 * TILE_B + s0, Bhi + gB0 + kk);                      \
    cp_async16(base + 3 * TILE_B + s0, Blo + gB0 + kk);                      \
} while (0)

    float acc[2][4][4];
#pragma unroll
    for (int i = 0; i < 2; i++)
#pragma unroll
        for (int j = 0; j < 4; j++)
#pragma unroll
            for (int q = 0; q < 4; q++) acc[i][j][q] = 0.0f;

    const int l7 = lane & 7, m4 = lane >> 3;
    const unsigned aoff = (wm * 32 + (m4 & 1) * 8 + l7) * ROW_BYTES + (m4 >> 1) * 16;
    const unsigned boff = (wn * 32 + ((m4 & 2) ? 8 : 0) + l7) * ROW_BYTES + (m4 & 1) * 16;

    const int NCH = K / BK;

    LOAD_CHUNK(0, 0); CP_COMMIT();
    LOAD_CHUNK(1, 1); CP_COMMIT();

    for (int c = 0; c < NCH; c++) {
        cp_wait<1>();
        __syncthreads();

        if (c + 2 < NCH) LOAD_CHUNK(c + 2, (c + 2) % NSTAGE);
        CP_COMMIT();

        const unsigned stg = sb + (c % NSTAGE) * STAGE_B;
#pragma unroll
        for (int ks = 0; ks < 2; ks++) {
            const unsigned kb = ks * 32;
            unsigned ah[2][4], al[2][4], bh[2][4], bl[2][4];
#pragma unroll
            for (int mi = 0; mi < 2; mi++) {
                unsigned ad = stg + aoff + mi * (16 * ROW_BYTES) + kb;
                ldm_x4(ad + 0 * TILE_B, ah[mi]);
                ldm_x4(ad + 1 * TILE_B, al[mi]);
            }
#pragma unroll
            for (int ng = 0; ng < 2; ng++) {
                unsigned bd = stg + boff + ng * (16 * ROW_BYTES) + kb;
                ldm_x4(bd + 2 * TILE_B, bh[ng]);
                ldm_x4(bd + 3 * TILE_B, bl[ng]);
            }
#pragma unroll
            for (int mi = 0; mi < 2; mi++)
#pragma unroll
                for (int ni = 0; ni < 4; ni++) {
                    const int ng = ni >> 1, half = (ni & 1) * 2;
                    unsigned bhr[2] = { bh[ng][half], bh[ng][half + 1] };
                    unsigned blr[2] = { bl[ng][half], bl[ng][half + 1] };
                    mma_bf16(acc[mi][ni], ah[mi], bhr);
                    mma_bf16(acc[mi][ni], ah[mi], blr);
                    mma_bf16(acc[mi][ni], al[mi], bhr);
                }
        }
        __syncthreads();
    }

    const int erow = row0 + wm * 32 + (lane >> 2);
    const int ecol = col0 + wn * 32 + (lane & 3) * 2;
#pragma unroll
    for (int mi = 0; mi < 2; mi++)
#pragma unroll
        for (int ni = 0; ni < 4; ni++) {
            const size_t o0 = (size_t)(erow + mi * 16) * N + ecol + ni * 8;
            const size_t o1 = o0 + (size_t)8 * N;
            if (MODE == 0) {
                C[o0] = acc[mi][ni][0]; C[o0 + 1] = acc[mi][ni][1];
                C[o1] = acc[mi][ni][2]; C[o1 + 1] = acc[mi][ni][3];
            } else {
                unsigned h0, l0w, h1, l1w;
                split2(acc[mi][ni][0], acc[mi][ni][1], h0, l0w);
                split2(acc[mi][ni][2], acc[mi][ni][3], h1, l1w);
                *(unsigned*)(Chi + o0) = h0;
                *(unsigned*)(Clo + o0) = l0w;
                *(unsigned*)(Chi + o1) = h1;
                *(unsigned*)(Clo + o1) = l1w;
            }
        }
#undef LOAD_CHUNK
}

__global__ __launch_bounds__(GT) void gemm_mma(
    const __nv_bfloat16* __restrict__ Ahi, const __nv_bfloat16* __restrict__ Alo,
    const __nv_bfloat16* __restrict__ Bhi, const __nv_bfloat16* __restrict__ Blo,
    float* __restrict__ C, int M, int N, int K)
{
    gemm_body<0>(Ahi, Alo, Bhi, Blo, C, nullptr, nullptr, M, N, K,
                 blockIdx.y * 128, blockIdx.x * 128);
}

// Fused QKV: z=0 -> q fp32, z=1 -> k fp32, z=2 -> v split bf16.
__global__ __launch_bounds__(GT) void gemm_qkv(
    const __nv_bfloat16* __restrict__ Ahi, const __nv_bfloat16* __restrict__ Alo,
    const __nv_bfloat16* __restrict__ Whi, const __nv_bfloat16* __restrict__ Wlo,
    float* __restrict__ Cq, float* __restrict__ Ck,
    __nv_bfloat16* __restrict__ Vhi, __nv_bfloat16* __restrict__ Vlo)
{
    const size_t WSZ = (size_t)DIMM * DIMM;
    const int z = blockIdx.z;
    const __nv_bfloat16* Bhi = Whi + (size_t)z * WSZ;
    const __nv_bfloat16* Blo = Wlo + (size_t)z * WSZ;
    if (z == 2) {
        gemm_body<1>(Ahi, Alo, Bhi, Blo, nullptr, Vhi, Vlo, BS, DIMM, DIMM,
                     blockIdx.y * 128, blockIdx.x * 128);
    } else {
        float* C = (z == 0) ? Cq : Ck;
        gemm_body<0>(Ahi, Alo, Bhi, Blo, C, nullptr, nullptr, BS, DIMM, DIMM,
                     blockIdx.y * 128, blockIdx.x * 128);
    }
}

// ---------------------------------------------------------------------------
// Flash attention (unchanged from R7)
// ---------------------------------------------------------------------------
#define FROWB  144
#define FTILE  (128 * FROWB)
#define FSTAGE (4 * FTILE)
#define FLASH_SMEM (2 * FTILE + 2 * FSTAGE)

__global__ __launch_bounds__(256, 1) void flash_mma(
    const __nv_bfloat16* __restrict__ qhi, const __nv_bfloat16* __restrict__ qlo,
    const __nv_bfloat16* __restrict__ khi, const __nv_bfloat16* __restrict__ klo,
    const __nv_bfloat16* __restrict__ vhi, const __nv_bfloat16* __restrict__ vlo,
    const int* __restrict__ masks,
    __nv_bfloat16* __restrict__ aohi, __nv_bfloat16* __restrict__ aolo)
{
    extern __shared__ char smem[];
    const unsigned sb = smem_u32(smem);
    const int tid = threadIdx.x, lane = tid & 31, wid = tid >> 5;
    const int bh = blockIdx.y, b = bh >> 4, h = bh & 15;
    const int q0 = blockIdx.x * 128;
    const int wq0 = wid * 16;

    const unsigned sQh = sb, sQl = sb + FTILE;

#pragma unroll
    for (int t = 0; t < 4; t++) {
        int seg = tid + t * 256, row = seg >> 3, s = seg & 7;
        size_t g = (size_t)(b * SS + q0 + row) * DIMM + h * HD + s * 8;
        unsigned sa = row * FROWB + s * 16;
        cp_async16(sQh + sa, qhi + g);
        cp_async16(sQl + sa, qlo + g);
    }

#define KV_LOAD(kt, stg) do {                                                \
    unsigned base = sb + 2 * FTILE + (stg) * FSTAGE;                         \
    _Pragma("unroll")                                                        \
    for (int t = 0; t < 4; t++) {                                            \
        int seg = tid + t * 256, row = seg >> 3, s = seg & 7;                \
        size_t g = (size_t)(b * SS + (kt) * 128 + row) * DIMM + h * HD + s * 8; \
        unsigned sa = row * FROWB + s * 16;                                  \
        cp_async16(base + sa,             khi + g);                          \
        cp_async16(base + FTILE + sa,     klo + g);                          \
        cp_async16(base + 2 * FTILE + sa, vhi + g);                          \
        cp_async16(base + 3 * FTILE + sa, vlo + g);                          \
    }                                                                        \
} while (0)

    KV_LOAD(0, 0); CP_COMMIT();
    KV_LOAD(1, 1); CP_COMMIT();

    float m0 = -1e30f, m1 = -1e30f, l0 = 0.0f, l1 = 0.0f;
    float acc_o[8][4];
#pragma unroll
    for (int j = 0; j < 8; j++)
#pragma unroll
        for (int q = 0; q < 4; q++) acc_o[j][q] = 0.0f;

    const int l7 = lane & 7, m4 = lane >> 3;
    const unsigned qoff = (wq0 + (m4 & 1) * 8 + l7) * FROWB + (m4 >> 1) * 16;
    const unsigned koff = (((m4 & 2) ? 8 : 0) + l7) * FROWB + (m4 & 1) * 16;
    const unsigned voff = (lane & 15) * FROWB + (lane >> 4) * 16;

    const int gr0 = q0 + wq0 + (lane >> 2);
    const int* mrow0 = masks + (size_t)b * SS * SS + (size_t)gr0 * SS;
    const int* mrow1 = mrow0 + 8 * SS;

    for (int kt = 0; kt < 8; kt++) {
        if (kt == 7) cp_wait<0>(); else cp_wait<1>();
        __syncthreads();
        const unsigned kbase = sb + 2 * FTILE + (kt & 1) * FSTAGE;

        float s[16][4];
#pragma unroll
        for (int ni = 0; ni < 16; ni++)
#pragma unroll
            for (int q = 0; q < 4; q++) s[ni][q] = 0.0f;

#pragma unroll
        for (int ks = 0; ks < 4; ks++) {
            unsigned ah[4], al[4];
            ldm_x4(sQh + qoff + ks * 32, ah);
            ldm_x4(sQl + qoff + ks * 32, al);
#pragma unroll
            for (int g = 0; g < 8; g++) {
                unsigned bh4[4], bl4[4];
                unsigned ba = kbase + koff + g * (16 * FROWB) + ks * 32;
                ldm_x4(ba, bh4);
                ldm_x4(ba + FTILE, bl4);
                unsigned bh0[2] = { bh4[0], bh4[1] }, bh1[2] = { bh4[2], bh4[3] };
                unsigned bl0[2] = { bl4[0], bl4[1] }, bl1[2] = { bl4[2], bl4[3] };
                mma_bf16(s[2 * g],     ah, bh0); mma_bf16(s[2 * g],     ah, bl0); mma_bf16(s[2 * g],     al, bh0);
                mma_bf16(s[2 * g + 1], ah, bh1); mma_bf16(s[2 * g + 1], ah, bl1); mma_bf16(s[2 * g + 1], al, bh1);
            }
        }

        const int kc0 = kt * 128 + (lane & 3) * 2;
#pragma unroll
        for (int ni = 0; ni < 16; ni++) {
            int2 mk0 = *(const int2*)(mrow0 + kc0 + ni * 8);
            int2 mk1 = *(const int2*)(mrow1 + kc0 + ni * 8);
            s[ni][0] = mk0.x ? s[ni][0] * 0.125f : NEG_INF_F;
            s[ni][1] = mk0.y ? s[ni][1] * 0.125f : NEG_INF_F;
            s[ni][2] = mk1.x ? s[ni][2] * 0.125f : NEG_INF_F;
            s[ni][3] = mk1.y ? s[ni][3] * 0.125f : NEG_INF_F;
        }

        float mx0 = -1e30f, mx1 = -1e30f;
#pragma unroll
        for (int ni = 0; ni < 16; ni++) {
            mx0 = fmaxf(mx0, fmaxf(s[ni][0], s[ni][1]));
            mx1 = fmaxf(mx1, fmaxf(s[ni][2], s[ni][3]));
        }
        mx0 = fmaxf(mx0, __shfl_xor_sync(0xffffffffu, mx0, 1));
        mx0 = fmaxf(mx0, __shfl_xor_sync(0xffffffffu, mx0, 2));
        mx1 = fmaxf(mx1, __shfl_xor_sync(0xffffffffu, mx1, 1));
        mx1 = fmaxf(mx1, __shfl_xor_sync(0xffffffffu, mx1, 2));

        float mn0 = fmaxf(m0, mx0), mn1 = fmaxf(m1, mx1);
        float al0 = __expf(m0 - mn0), al1 = __expf(m1 - mn1);
        m0 = mn0; m1 = mn1;

        float sum0 = 0.0f, sum1 = 0.0f;
#pragma unroll
        for (int ni = 0; ni < 16; ni++) {
            s[ni][0] = __expf(s[ni][0] - mn0);
            s[ni][1] = __expf(s[ni][1] - mn0);
            s[ni][2] = __expf(s[ni][2] - mn1);
            s[ni][3] = __expf(s[ni][3] - mn1);
            sum0 += s[ni][0] + s[ni][1];
            sum1 += s[ni][2] + s[ni][3];
        }
        sum0 += __shfl_xor_sync(0xffffffffu, sum0, 1);
        sum0 += __shfl_xor_sync(0xffffffffu, sum0, 2);
        sum1 += __shfl_xor_sync(0xffffffffu, sum1, 1);
        sum1 += __shfl_xor_sync(0xffffffffu, sum1, 2);
        l0 = l0 * al0 + sum0;
        l1 = l1 * al1 + sum1;

#pragma unroll
        for (int j = 0; j < 8; j++) {
            acc_o[j][0] *= al0; acc_o[j][1] *= al0;
            acc_o[j][2] *= al1; acc_o[j][3] *= al1;
        }

#pragma unroll
        for (int kc = 0; kc < 8; kc++) {
            unsigned aH[4], aL[4];
            split2(s[2 * kc][0],     s[2 * kc][1],     aH[0], aL[0]);
            split2(s[2 * kc][2],     s[2 * kc][3],     aH[1], aL[1]);
            split2(s[2 * kc + 1][0], s[2 * kc + 1][1], aH[2], aL[2]);
            split2(s[2 * kc + 1][2], s[2 * kc + 1][3], aH[3], aL[3]);
#pragma unroll
            for (int dg = 0; dg < 4; dg++) {
                unsigned bh4[4], bl4[4];
                unsigned va = kbase + 2 * FTILE + voff + kc * (16 * FROWB) + dg * 32;
                ldm_x4_t(va, bh4);
                ldm_x4_t(va + FTILE, bl4);
                unsigned b0h[2] = { bh4[0], bh4[1] }, b1h[2] = { bh4[2], bh4[3] };
                unsigned b0l[2] = { bl4[0], bl4[1] }, b1l[2] = { bl4[2], bl4[3] };
                mma_bf16(acc_o[2 * dg],     aH, b0h);
                mma_bf16(acc_o[2 * dg],     aH, b0l);
                mma_bf16(acc_o[2 * dg],     aL, b0h);
                mma_bf16(acc_o[2 * dg + 1], aH, b1h);
                mma_bf16(acc_o[2 * dg + 1], aH, b1l);
                mma_bf16(acc_o[2 * dg + 1], aL, b1h);
            }
        }

        __syncthreads();
        if (kt + 2 < 8) { KV_LOAD(kt + 2, kt & 1); CP_COMMIT(); }
    }

    const float inv0 = 1.0f / l0, inv1 = 1.0f / l1;
    const size_t o0 = (size_t)(b * SS + gr0) * DIMM + h * HD + (lane & 3) * 2;
    const size_t o1 = o0 + (size_t)8 * DIMM;
#pragma unroll
    for (int j = 0; j < 8; j++) {
        unsigned h0, w0, h1, w1;
        split2(acc_o[j][0] * inv0, acc_o[j][1] * inv0, h0, w0);
        split2(acc_o[j][2] * inv1, acc_o[j][3] * inv1, h1, w1);
        *(unsigned*)(aohi + o0 + j * 8) = h0;
        *(unsigned*)(aolo + o0 + j * 8) = w0;
        *(unsigned*)(aohi + o1 + j * 8) = h1;
        *(unsigned*)(aolo + o1 + j * 8) = w1;
    }
#undef KV_LOAD
}

// ---------------------------------------------------------------------------
// RoPE: reads fp32 q/k, writes split bf16 hi/lo directly.
// ---------------------------------------------------------------------------
#define ROT(xx, yy, c, s) { float _t = (xx)*(c) - (yy)*(s); (yy) = (xx)*(s) + (yy)*(c); (xx) = _t; }

__global__ __launch_bounds__(256) void rope_split(const float* __restrict__ q,
                                                  const float* __restrict__ k,
                                                  const int* __restrict__ Hm,
                                                  const int* __restrict__ Bm,
                                                  const float* __restrict__ fc,
                                                  const float* __restrict__ fs,
                                                  __nv_bfloat16* __restrict__ qhi,
                                                  __nv_bfloat16* __restrict__ qlo,
                                                  __nv_bfloat16* __restrict__ khi,
                                                  __nv_bfloat16* __restrict__ klo)
{
    const int tok = blockIdx.x;
    const int tid = threadIdx.x;
    const int h = tid >> 4;
    const int m = tid & 15;
    const int base = tok * DIMM + h * HD;

    float2 qab = *(const float2*)&q[base + 2 * m];
    float2 qcd = *(const float2*)&q[base + 2 * m + 32];
    float2 kab = *(const float2*)&k[base + 2 * m];
    float2 kcd = *(const float2*)&k[base + 2 * m + 32];

    const float cH0 = fc[32 + m],      sH0 = fs[32 + m];
    const float cH1 = fc[32 + m + 16], sH1 = fs[32 + m + 16];
    const float cB0a = fc[32 + 2 * m],     sB0a = fs[32 + 2 * m];
    const float cB0b = fc[32 + 2 * m + 1], sB0b = fs[32 + 2 * m + 1];
    const float cB1a = fc[64 + 2 * m],     sB1a = fs[64 + 2 * m];
    const float cB1b = fc[64 + 2 * m + 1], sB1b = fs[64 + 2 * m + 1];

#pragma unroll
    for (int i = 0; i < 6; i++) {
        if (Hm[i * BS + tok]) {
            ROT(qab.x, qab.y, cH0, sH0); ROT(qcd.x, qcd.y, cH1, sH1);
            ROT(kab.x, kab.y, cH0, sH0); ROT(kcd.x, kcd.y, cH1, sH1);
        }
        if (Bm[(i * 2 + 0) * BS + tok]) {
            ROT(qab.x, qcd.x, cB0a, sB0a); ROT(qab.y, qcd.y, cB0b, sB0b);
            ROT(kab.x, kcd.x, cB0a, sB0a); ROT(kab.y, kcd.y, cB0b, sB0b);
        }
        if (Bm[(i * 2 + 1) * BS + tok]) {
            ROT(qab.x, qcd.x, cB1a, sB1a); ROT(qab.y, qcd.y, cB1b, sB1b);
            ROT(kab.x, kcd.x, cB1a, sB1a); ROT(kab.y, kcd.y, cB1b, sB1b);
        }
    }

    unsigned hw, lw;
    split2(qab.x, qab.y, hw, lw);
    *(unsigned*)(qhi + base + 2 * m) = hw;  *(unsigned*)(qlo + base + 2 * m) = lw;
    split2(qcd.x, qcd.y, hw, lw);
    *(unsigned*)(qhi + base + 2 * m + 32) = hw;  *(unsigned*)(qlo + base + 2 * m + 32) = lw;
    split2(kab.x, kab.y, hw, lw);
    *(unsigned*)(khi + base + 2 * m) = hw;  *(unsigned*)(klo + base + 2 * m) = lw;
    split2(kcd.x, kcd.y, hw, lw);
    *(unsigned*)(khi + base + 2 * m + 32) = hw;  *(unsigned*)(klo + base + 2 * m + 32) = lw;
}

// ---------------------------------------------------------------------------
extern "C" void kernel_launch(void* const* d_in, const int* in_sizes, int n_in,
                              void* d_out, int out_size)
{
    const float* x     = (const float*)d_in[0];
    const int*   masks = (const int*)d_in[1];
    const int*   Hm    = (const int*)d_in[2];
    const int*   Bm    = (const int*)d_in[3];
    const float* fc    = (const float*)d_in[4];
    const float* fs    = (const float*)d_in[5];
    const float* wq    = (const float*)d_in[6];
    const float* wk    = (const float*)d_in[7];
    const float* wv    = (const float*)d_in[8];
    const float* wo    = (const float*)d_in[9];
    float* out = (float*)d_out;

    float *gq, *gk;
    __nv_bfloat16 *xhi, *xlo, *aohi, *aolo, *whi, *wlo;
    __nv_bfloat16 *qhi, *qlo, *khi, *klo, *vhi, *vlo;
    cudaGetSymbolAddress((void**)&gq,   g_q);
    cudaGetSymbolAddress((void**)&gk,   g_k);
    cudaGetSymbolAddress((void**)&xhi,  g_xhi);
    cudaGetSymbolAddress((void**)&xlo,  g_xlo);
    cudaGetSymbolAddress((void**)&aohi, g_aohi);
    cudaGetSymbolAddress((void**)&aolo, g_aolo);
    cudaGetSymbolAddress((void**)&whi,  g_whi);
    cudaGetSymbolAddress((void**)&wlo,  g_wlo);
    cudaGetSymbolAddress((void**)&qhi,  g_qhi);
    cudaGetSymbolAddress((void**)&qlo,  g_qlo);
    cudaGetSymbolAddress((void**)&khi,  g_khi);
    cudaGetSymbolAddress((void**)&klo,  g_klo);
    cudaGetSymbolAddress((void**)&vhi,  g_vhi);
    cudaGetSymbolAddress((void**)&vlo,  g_vlo);

    static bool attr_done = false;
    if (!attr_done) {
        cudaFuncSetAttribute(gemm_mma,  cudaFuncAttributeMaxDynamicSharedMemorySize, GEMM_SMEM);
        cudaFuncSetAttribute(gemm_qkv,  cudaFuncAttributeMaxDynamicSharedMemorySize, GEMM_SMEM);
        cudaFuncSetAttribute(flash_mma, cudaFuncAttributeMaxDynamicSharedMemorySize, FLASH_SMEM);
        attr_done = true;
    }

    prep_w4<<<dim3(32, 32, 4), 256>>>(wq, wk, wv, wo, whi, wlo);

    split_f32<<<BS * DIMM / 4 / 256, 256>>>((const float4*)x, xhi, xlo);

    gemm_qkv<<<dim3(DIMM / 128, BS / 128, 3), GT, GEMM_SMEM>>>(
        xhi, xlo, whi, wlo, gq, gk, vhi, vlo);

    rope_split<<<BS, 256>>>(gq, gk, Hm, Bm, fc, fs, qhi, qlo, khi, klo);

    flash_mma<<<dim3(SS / 128, BB * NH), 256, FLASH_SMEM>>>(
        qhi, qlo, khi, klo, vhi, vlo, masks, aohi, aolo);

    gemm_mma<<<dim3(DIMM / 128, BS / 128), GT, GEMM_SMEM>>>(
        aohi, aolo, whi + 3 * (size_t)DIMM * DIMM, wlo + 3 * (size_t)DIMM * DIMM,
        out, BS, DIMM, DIMM);
}